// round 6
// baseline (speedup 1.0000x reference)
#include <cuda_runtime.h>
#include <cuda_bf16.h>
#include <math.h>
#include <stdint.h>

// Problem constants
#define BSZ   4096
#define HDIM  300
#define TT    43
#define NCLS  80

// GEMM shapes (x-precompute)
#define MROWS 2560          // 2 dirs * 1280 gate-rows (gate-interleaved, padded)
#define KDIM  320           // 300 padded
#define NCOLS 176128        // 43*4096
#define MTILES 20
#define NTILES 1376
// recurrence
#define NDR   1280          // gate rows per direction (320 units * 4 gates)
#define KH    320           // h k-dim padded

// ---------------- device scratch ----------------------------------------------
__device__ __nv_bfloat16 g_Wh[(size_t)MROWS * KDIM];         // W_ih hi  [row'][k]
__device__ __nv_bfloat16 g_Wl[(size_t)MROWS * KDIM];
__device__ __nv_bfloat16 g_Xh[(size_t)NCOLS * KDIM];         // X hi  [col=(t*4096+b)][k]
__device__ __nv_bfloat16 g_Xl[(size_t)NCOLS * KDIM];
__device__ float         g_zx2[(size_t)NCOLS * MROWS];       // [col][row']  z_x + bias
__device__ float         g_bias2560[MROWS];
__device__ __nv_bfloat16 g_WHh[(size_t)2 * NDR * KH];        // W_hh hi [d][row'][k]
__device__ __nv_bfloat16 g_WHl[(size_t)2 * NDR * KH];
__device__ __nv_bfloat16 g_Hh[(size_t)2 * 2 * BSZ * KH];     // [buf][d][b][k]
__device__ __nv_bfloat16 g_Hl[(size_t)2 * 2 * BSZ * KH];
__device__ float         g_c [(size_t)2 * BSZ * KH];         // [d][b][u]
__device__ float         g_hs2[(size_t)BSZ * TT * 2 * KH];   // [b][t][d*320+u]

// ---------------- math helpers -------------------------------------------------
__device__ __forceinline__ float fsig(float x) {
    return __fdividef(1.0f, 1.0f + __expf(-x));
}
__device__ __forceinline__ float ftanh_(float x) {
    float e = __expf(2.0f * x);
    return 1.0f - __fdividef(2.0f, e + 1.0f);
}
__device__ __forceinline__ uint32_t smem_u32(const void* p) {
    uint32_t a;
    asm("{ .reg .u64 t; cvta.to.shared.u64 t, %1; cvt.u32.u64 %0, t; }" : "=r"(a) : "l"(p));
    return a;
}
__device__ __forceinline__ void mma16816(float* c, const uint32_t* a, const uint32_t* b) {
    asm volatile(
        "mma.sync.aligned.m16n8k16.row.col.f32.bf16.bf16.f32 "
        "{%0,%1,%2,%3}, {%4,%5,%6,%7}, {%8,%9}, {%0,%1,%2,%3};"
        : "+f"(c[0]), "+f"(c[1]), "+f"(c[2]), "+f"(c[3])
        : "r"(a[0]), "r"(a[1]), "r"(a[2]), "r"(a[3]), "r"(b[0]), "r"(b[1]));
}
#define LDSM4(r0, r1, r2, r3, addr)                                               \
    asm volatile("ldmatrix.sync.aligned.m8n8.x4.shared.b16 {%0,%1,%2,%3}, [%4];"  \
                 : "=r"(r0), "=r"(r1), "=r"(r2), "=r"(r3) : "r"(addr))

// ---------------- prep kernels -------------------------------------------------
// W_ih, gate-interleaved rows: row' = d*1280 + u*4 + gate
__global__ void prep_wsplit_kernel(const float* __restrict__ wih) {
    int idx = blockIdx.x * blockDim.x + threadIdx.x;
    if (idx >= MROWS * KDIM) return;
    int row = idx / KDIM, k = idx % KDIM;
    int d = row / NDR, r = row % NDR;
    int u = r >> 2, gate = r & 3;
    float v = 0.f;
    if (u < 300 && k < 300)
        v = wih[((size_t)d * 1200 + gate * 300 + u) * 300 + k];
    __nv_bfloat16 hi = __float2bfloat16(v);
    g_Wh[idx] = hi;
    g_Wl[idx] = __float2bfloat16(v - __bfloat162float(hi));
}

// W_hh, same row ordering
__global__ void prep_whhsplit_kernel(const float* __restrict__ whh) {
    int idx = blockIdx.x * blockDim.x + threadIdx.x;
    if (idx >= 2 * NDR * KH) return;
    int row = idx / KH, k = idx % KH;
    int d = row / NDR, r = row % NDR;
    int u = r >> 2, gate = r & 3;
    float v = 0.f;
    if (u < 300 && k < 300)
        v = whh[((size_t)d * 1200 + gate * 300 + u) * 300 + k];
    __nv_bfloat16 hi = __float2bfloat16(v);
    g_WHh[idx] = hi;
    g_WHl[idx] = __float2bfloat16(v - __bfloat162float(hi));
}

// X split: col n = t*4096+b; value x[b][k][t]
__global__ void prep_xsplit_kernel(const float* __restrict__ x) {
    size_t idx = (size_t)blockIdx.x * blockDim.x + threadIdx.x;
    if (idx >= (size_t)NCOLS * KDIM) return;
    size_t n = idx / KDIM;
    int k = (int)(idx % KDIM);
    int t = (int)(n >> 12);
    int b = (int)(n & 4095);
    float v = (k < 300) ? x[((size_t)b * 300 + k) * TT + t] : 0.f;
    __nv_bfloat16 hi = __float2bfloat16(v);
    g_Xh[idx] = hi;
    g_Xl[idx] = __float2bfloat16(v - __bfloat162float(hi));
}

__global__ void prep_bias_kernel(const float* __restrict__ bih, const float* __restrict__ bhh) {
    int row = blockIdx.x * blockDim.x + threadIdx.x;
    if (row >= MROWS) return;
    int d = row / NDR, r = row % NDR;
    int u = r >> 2, gate = r & 3;
    float v = 0.f;
    if (u < 300)
        v = bih[(size_t)d * 1200 + gate * 300 + u] + bhh[(size_t)d * 1200 + gate * 300 + u];
    g_bias2560[row] = v;
}

// zero h(t=0) buf 0 + c state
__global__ void zero_state_kernel() {
    size_t i = (size_t)blockIdx.x * blockDim.x + threadIdx.x;
    size_t n = (size_t)2 * BSZ * KH;
    if (i >= n) return;
    g_c[i] = 0.f;
    g_Hh[i] = __float2bfloat16(0.f);
    g_Hl[i] = __float2bfloat16(0.f);
}

// ---------------- x-precompute GEMM: g_zx2[n][m'] = W_ih @ X + bias ------------
#define GS_BYTES 73728
#define TROWB 144

__global__ __launch_bounds__(256, 2)
void gemm_zx_kernel() {
    extern __shared__ char sm[];
    char* Ah = sm;
    char* Al = sm + 18432;
    char* Bh = sm + 36864;
    char* Bl = sm + 55296;
    const int tid  = threadIdx.x;
    const int lane = tid & 31;
    const int wid  = tid >> 5;
    const int wm   = wid & 1;
    const int wn   = wid >> 1;
    const int m0   = blockIdx.x * 128;
    const int n0   = blockIdx.y * 128;

    const uint32_t aRowByte =
        (uint32_t)(wm * 64 + ((lane >> 3) & 1) * 8 + (lane & 7)) * TROWB + (lane >> 4) * 16;
    const uint32_t bRowByte =
        (uint32_t)(wn * 32 + (lane >> 4) * 8 + (lane & 7)) * TROWB + ((lane >> 3) & 1) * 16;
    const uint32_t baseAh = smem_u32(Ah), baseAl = smem_u32(Al);
    const uint32_t baseBh = smem_u32(Bh), baseBl = smem_u32(Bl);

    float acc[4][4][4];
    #pragma unroll
    for (int mt = 0; mt < 4; mt++)
        #pragma unroll
        for (int nt = 0; nt < 4; nt++)
            #pragma unroll
            for (int i = 0; i < 4; i++) acc[mt][nt][i] = 0.f;

    for (int chunk = 0; chunk < 5; chunk++) {
        const int kc0 = chunk * 64;
        __syncthreads();
        for (int i = tid; i < 1024; i += 256) {
            int r = i >> 3, c8 = i & 7;
            uint32_t off = (uint32_t)r * TROWB + c8 * 16;
            size_t sa = (size_t)(m0 + r) * KDIM + kc0 + c8 * 8;
            size_t sb = (size_t)(n0 + r) * KDIM + kc0 + c8 * 8;
            *(uint4*)(Ah + off) = *(const uint4*)(g_Wh + sa);
            *(uint4*)(Al + off) = *(const uint4*)(g_Wl + sa);
            *(uint4*)(Bh + off) = *(const uint4*)(g_Xh + sb);
            *(uint4*)(Bl + off) = *(const uint4*)(g_Xl + sb);
        }
        __syncthreads();

        #pragma unroll
        for (int ks = 0; ks < 4; ks++) {
            const uint32_t kbb = ks * 32;
            uint32_t aF[4][4], bHF[4][2], bLF[4][2];
            #pragma unroll
            for (int mt = 0; mt < 4; mt++)
                LDSM4(aF[mt][0], aF[mt][1], aF[mt][2], aF[mt][3],
                      baseAh + aRowByte + mt * (16 * TROWB) + kbb);
            #pragma unroll
            for (int p = 0; p < 2; p++)
                LDSM4(bHF[2 * p][0], bHF[2 * p][1], bHF[2 * p + 1][0], bHF[2 * p + 1][1],
                      baseBh + bRowByte + p * (16 * TROWB) + kbb);
            #pragma unroll
            for (int p = 0; p < 2; p++)
                LDSM4(bLF[2 * p][0], bLF[2 * p][1], bLF[2 * p + 1][0], bLF[2 * p + 1][1],
                      baseBl + bRowByte + p * (16 * TROWB) + kbb);
            #pragma unroll
            for (int mt = 0; mt < 4; mt++)
                #pragma unroll
                for (int nt = 0; nt < 4; nt++)
                    mma16816(acc[mt][nt], aF[mt], bHF[nt]);
            #pragma unroll
            for (int mt = 0; mt < 4; mt++)
                #pragma unroll
                for (int nt = 0; nt < 4; nt++)
                    mma16816(acc[mt][nt], aF[mt], bLF[nt]);
            #pragma unroll
            for (int mt = 0; mt < 4; mt++)
                LDSM4(aF[mt][0], aF[mt][1], aF[mt][2], aF[mt][3],
                      baseAl + aRowByte + mt * (16 * TROWB) + kbb);
            #pragma unroll
            for (int mt = 0; mt < 4; mt++)
                #pragma unroll
                for (int nt = 0; nt < 4; nt++)
                    mma16816(acc[mt][nt], aF[mt], bHF[nt]);
        }
    }

    const int rbase = m0 + wm * 64 + (lane >> 2);
    const int nbase = n0 + wn * 32 + (lane & 3) * 2;
    #pragma unroll
    for (int mt = 0; mt < 4; mt++) {
        int row = rbase + mt * 16;
        float br0 = g_bias2560[row];
        float br8 = g_bias2560[row + 8];
        #pragma unroll
        for (int nt = 0; nt < 4; nt++) {
            size_t n = (size_t)(nbase + nt * 8);
            g_zx2[n * MROWS + row]           = acc[mt][nt][0] + br0;
            g_zx2[(n + 1) * MROWS + row]     = acc[mt][nt][1] + br0;
            g_zx2[n * MROWS + row + 8]       = acc[mt][nt][2] + br8;
            g_zx2[(n + 1) * MROWS + row + 8] = acc[mt][nt][3] + br8;
        }
    }
}

// ---------------- per-step recurrent GEMM + fused gate epilogue -----------------
// m = batch (128/CTA), n = gate rows within direction (128/CTA), k = h (320)
__global__ __launch_bounds__(256, 2)
void step_kernel(int t) {
    extern __shared__ char sm[];
    char* Ah = sm;
    char* Al = sm + 18432;
    char* Bh = sm + 36864;
    char* Bl = sm + 55296;
    const int tid  = threadIdx.x;
    const int lane = tid & 31;
    const int wid  = tid >> 5;
    const int wm   = wid & 1;
    const int wn   = wid >> 1;
    const int m0   = blockIdx.x * 128;     // batch
    const int n0   = blockIdx.y * 128;     // gate row within dir
    const int d    = blockIdx.z;
    const int p    = t & 1;                // read buffer
    const int q    = 1 - p;                // write buffer

    const __nv_bfloat16* HhB = g_Hh + (size_t)(p * 2 + d) * BSZ * KH;
    const __nv_bfloat16* HlB = g_Hl + (size_t)(p * 2 + d) * BSZ * KH;
    const __nv_bfloat16* WhB = g_WHh + (size_t)d * NDR * KH;
    const __nv_bfloat16* WlB = g_WHl + (size_t)d * NDR * KH;

    const uint32_t aRowByte =
        (uint32_t)(wm * 64 + ((lane >> 3) & 1) * 8 + (lane & 7)) * TROWB + (lane >> 4) * 16;
    const uint32_t bRowByte =
        (uint32_t)(wn * 32 + (lane >> 4) * 8 + (lane & 7)) * TROWB + ((lane >> 3) & 1) * 16;
    const uint32_t baseAh = smem_u32(Ah), baseAl = smem_u32(Al);
    const uint32_t baseBh = smem_u32(Bh), baseBl = smem_u32(Bl);

    float acc[4][4][4];
    #pragma unroll
    for (int mt = 0; mt < 4; mt++)
        #pragma unroll
        for (int nt = 0; nt < 4; nt++)
            #pragma unroll
            for (int i = 0; i < 4; i++) acc[mt][nt][i] = 0.f;

    for (int chunk = 0; chunk < 5; chunk++) {
        const int kc0 = chunk * 64;
        __syncthreads();
        for (int i = tid; i < 1024; i += 256) {
            int r = i >> 3, c8 = i & 7;
            uint32_t off = (uint32_t)r * TROWB + c8 * 16;
            size_t sa = (size_t)(m0 + r) * KH + kc0 + c8 * 8;
            size_t sb = (size_t)(n0 + r) * KH + kc0 + c8 * 8;
            *(uint4*)(Ah + off) = *(const uint4*)(HhB + sa);
            *(uint4*)(Al + off) = *(const uint4*)(HlB + sa);
            *(uint4*)(Bh + off) = *(const uint4*)(WhB + sb);
            *(uint4*)(Bl + off) = *(const uint4*)(WlB + sb);
        }
        __syncthreads();

        #pragma unroll
        for (int ks = 0; ks < 4; ks++) {
            const uint32_t kbb = ks * 32;
            uint32_t aF[4][4], bHF[4][2], bLF[4][2];
            #pragma unroll
            for (int mt = 0; mt < 4; mt++)
                LDSM4(aF[mt][0], aF[mt][1], aF[mt][2], aF[mt][3],
                      baseAh + aRowByte + mt * (16 * TROWB) + kbb);
            #pragma unroll
            for (int pp = 0; pp < 2; pp++)
                LDSM4(bHF[2 * pp][0], bHF[2 * pp][1], bHF[2 * pp + 1][0], bHF[2 * pp + 1][1],
                      baseBh + bRowByte + pp * (16 * TROWB) + kbb);
            #pragma unroll
            for (int pp = 0; pp < 2; pp++)
                LDSM4(bLF[2 * pp][0], bLF[2 * pp][1], bLF[2 * pp + 1][0], bLF[2 * pp + 1][1],
                      baseBl + bRowByte + pp * (16 * TROWB) + kbb);
            #pragma unroll
            for (int mt = 0; mt < 4; mt++)
                #pragma unroll
                for (int nt = 0; nt < 4; nt++)
                    mma16816(acc[mt][nt], aF[mt], bHF[nt]);
            #pragma unroll
            for (int mt = 0; mt < 4; mt++)
                #pragma unroll
                for (int nt = 0; nt < 4; nt++)
                    mma16816(acc[mt][nt], aF[mt], bLF[nt]);
            #pragma unroll
            for (int mt = 0; mt < 4; mt++)
                LDSM4(aF[mt][0], aF[mt][1], aF[mt][2], aF[mt][3],
                      baseAl + aRowByte + mt * (16 * TROWB) + kbb);
            #pragma unroll
            for (int mt = 0; mt < 4; mt++)
                #pragma unroll
                for (int nt = 0; nt < 4; nt++)
                    mma16816(acc[mt][nt], aF[mt], bHF[nt]);
        }
    }

    // ---- fused gate epilogue ----
    __nv_bfloat16* HhO = g_Hh + (size_t)(q * 2 + d) * BSZ * KH;
    __nv_bfloat16* HlO = g_Hl + (size_t)(q * 2 + d) * BSZ * KH;
    float* cS = g_c + (size_t)d * BSZ * KH;
    const float* zxT = g_zx2 + (size_t)t * 4096 * MROWS;
    const int rbase = m0 + wm * 64 + (lane >> 2);
    const int cb = n0 + wn * 32 + (lane & 3) * 2;
    const int l1 = lane & 1;

    #pragma unroll
    for (int mt = 0; mt < 4; mt++) {
        int bA = rbase + mt * 16;
        int bB = bA + 8;
        #pragma unroll
        for (int nt = 0; nt < 4; nt++) {
            int nc = cb + nt * 8;                     // [0, 1280)
            size_t zA = (size_t)bA * MROWS + d * NDR + nc;
            size_t zB = (size_t)bB * MROWS + d * NDR + nc;
            float a0 = acc[mt][nt][0] + zxT[zA];
            float a1 = acc[mt][nt][1] + zxT[zA + 1];
            float a2 = acc[mt][nt][2] + zxT[zB];
            float a3 = acc[mt][nt][3] + zxT[zB + 1];
            float v0 = __shfl_xor_sync(0xffffffffu, a0, 1);
            float v1 = __shfl_xor_sync(0xffffffffu, a1, 1);
            float v2 = __shfl_xor_sync(0xffffffffu, a2, 1);
            float v3 = __shfl_xor_sync(0xffffffffu, a3, 1);
            // even lane: (i,f)=(a0,a1) (g,o)=(v0,v1), row bA
            // odd  lane: (i,f)=(v2,v3) (g,o)=(a2,a3), row bB
            float zi = l1 ? v2 : a0;
            float zf = l1 ? v3 : a1;
            float zg = l1 ? a2 : v0;
            float zo = l1 ? a3 : v1;
            int b = l1 ? bB : bA;
            int u = nc >> 2;                          // unit within dir [0,320)
            size_t ci = (size_t)b * KH + u;
            float co = cS[ci];
            float cn = fsig(zf) * co + fsig(zi) * ftanh_(zg);
            cS[ci] = cn;
            float h = fsig(zo) * ftanh_(cn);
            __nv_bfloat16 hh = __float2bfloat16(h);
            HhO[ci] = hh;
            HlO[ci] = __float2bfloat16(h - __bfloat162float(hh));
            g_hs2[((size_t)b * TT + t) * (2 * KH) + d * KH + u] = h;
        }
    }
}

// ---------------- attention + FC epilogue --------------------------------------
#define ATT_SMEM 119856

__global__ __launch_bounds__(256, 1)
void attn_kernel(const float* __restrict__ conv_w,
                 const float* __restrict__ fc_w,
                 const float* __restrict__ fc_b,
                 float* __restrict__ out) {
    extern __shared__ char smem[];
    float* fcT   = (float*)smem;               // [300][80]
    float* hstar = (float*)(smem + 96000);     // [16][300]
    float* cw    = (float*)(smem + 115200);    // [300]
    float* e_sh  = cw + 300;                   // [16][44]
    float* l_sh  = e_sh + 704;                 // [80]
    float* p_sh  = l_sh + 80;                  // [80]

    const int tid = threadIdx.x;
    const int b0  = blockIdx.x * 16;

    for (int i = tid; i < 300; i += 256) cw[i] = conv_w[i];
    for (int i = tid; i < 300 * NCLS; i += 256) {
        int u = i / NCLS, cls = i - u * NCLS;
        fcT[i] = fc_w[(size_t)cls * 300 + u];
    }
    __syncthreads();

    // Phase A: e[b][t] = sum_u tanh(h0+h1) * cw[u]
    {
        int wid = tid >> 5, lane = tid & 31;
        for (int task = wid; task < 16 * TT; task += 8) {
            int b = task / TT, t = task - b * TT;
            const float* hp = g_hs2 + ((size_t)(b0 + b) * TT + t) * (2 * KH);
            float s = 0.f;
            for (int u = lane; u < 300; u += 32)
                s += ftanh_(hp[u] + hp[KH + u]) * cw[u];
            #pragma unroll
            for (int o = 16; o > 0; o >>= 1) s += __shfl_xor_sync(0xffffffffu, s, o);
            if (lane == 0) e_sh[b * 44 + t] = s;
        }
    }
    __syncthreads();

    if (tid < 16) {
        float m = -1e30f;
        for (int t = 0; t < TT; t++) m = fmaxf(m, e_sh[tid * 44 + t]);
        float ss = 0.f;
        for (int t = 0; t < TT; t++) { float pz = __expf(e_sh[tid * 44 + t] - m); e_sh[tid * 44 + t] = pz; ss += pz; }
        float inv = 1.0f / ss;
        for (int t = 0; t < TT; t++) e_sh[tid * 44 + t] *= inv;
    }
    __syncthreads();

    // Phase B: hstar[b][u] = tanh(sum_t (h0+h1) * alpha)
    for (int i = tid; i < 16 * 300; i += 256) {
        int b = i / 300, u = i - b * 300;
        const float* hp = g_hs2 + ((size_t)(b0 + b) * TT) * (2 * KH) + u;
        float acc = 0.f;
        for (int t = 0; t < TT; t++)
            acc += (hp[(size_t)t * (2 * KH)] + hp[(size_t)t * (2 * KH) + KH]) * e_sh[b * 44 + t];
        hstar[i] = ftanh_(acc);
    }
    __syncthreads();

    // FC + class softmax
    for (int b = 0; b < 16; b++) {
        if (tid < NCLS) {
            float acc = fc_b[tid];
            const float* hv = hstar + b * 300;
            for (int u = 0; u < 300; u++) acc += hv[u] * fcT[u * NCLS + tid];
            l_sh[tid] = acc;
        }
        __syncthreads();
        if (tid < NCLS) {
            float m = -1e30f;
            for (int j = 0; j < NCLS; j++) m = fmaxf(m, l_sh[j]);
            p_sh[tid] = __expf(l_sh[tid] - m);
        }
        __syncthreads();
        if (tid < NCLS) {
            float s = 0.f;
            for (int j = 0; j < NCLS; j++) s += p_sh[j];
            out[(size_t)(b0 + b) * NCLS + tid] = p_sh[tid] / s;
        }
        __syncthreads();
    }
}

// ---------------- launch --------------------------------------------------------
extern "C" void kernel_launch(void* const* d_in, const int* in_sizes, int n_in,
                              void* d_out, int out_size) {
    const float* x      = (const float*)d_in[0];
    const float* w_ih   = (const float*)d_in[1];
    const float* w_hh   = (const float*)d_in[2];
    const float* b_ih   = (const float*)d_in[3];
    const float* b_hh   = (const float*)d_in[4];
    const float* conv_w = (const float*)d_in[5];
    const float* fc_w   = (const float*)d_in[6];
    const float* fc_b   = (const float*)d_in[7];
    float* out = (float*)d_out;

    cudaFuncSetAttribute(gemm_zx_kernel, cudaFuncAttributeMaxDynamicSharedMemorySize, GS_BYTES);
    cudaFuncSetAttribute(step_kernel,    cudaFuncAttributeMaxDynamicSharedMemorySize, GS_BYTES);
    cudaFuncSetAttribute(attn_kernel,    cudaFuncAttributeMaxDynamicSharedMemorySize, ATT_SMEM);

    prep_wsplit_kernel<<<(MROWS * KDIM + 255) / 256, 256>>>(w_ih);
    prep_whhsplit_kernel<<<(2 * NDR * KH + 255) / 256, 256>>>(w_hh);
    prep_xsplit_kernel<<<(int)(((size_t)NCOLS * KDIM + 255) / 256), 256>>>(x);
    prep_bias_kernel<<<(MROWS + 255) / 256, 256>>>(b_ih, b_hh);
    zero_state_kernel<<<(int)(((size_t)2 * BSZ * KH + 255) / 256), 256>>>();

    gemm_zx_kernel<<<dim3(MTILES, NTILES), 256, GS_BYTES>>>();

    for (int t = 0; t < TT; t++)
        step_kernel<<<dim3(32, 10, 2), 256, GS_BYTES>>>(t);

    attn_kernel<<<BSZ / 16, 256, ATT_SMEM>>>(conv_w, fc_w, fc_b, out);
}

// round 8
// speedup vs baseline: 2.1255x; 2.1255x over previous
#include <cuda_runtime.h>
#include <cuda_bf16.h>
#include <math.h>
#include <stdint.h>

// Problem constants
#define BSZ   4096
#define HDIM  300
#define TT    43
#define NCLS  80

// GEMM shapes (x-precompute): m = 2560 weight rows, n = 176128 (t,b) cols
#define MROWS 2560
#define KDIM  320
#define NCOLS 176128
#define MTILES 20
#define NTILES 1376
// recurrence
#define NDR   1280          // gate rows per direction (320 units * 4 gates)
#define KH    320

// ---------------- device scratch ----------------------------------------------
__device__ __nv_bfloat16 g_Wh[(size_t)MROWS * KDIM];         // W_ih hi  [row'][k]
__device__ __nv_bfloat16 g_Wl[(size_t)MROWS * KDIM];
__device__ __nv_bfloat16 g_Xh[(size_t)NCOLS * KDIM];         // X hi  [col=(t*4096+b)][k]
__device__ __nv_bfloat16 g_Xl[(size_t)NCOLS * KDIM];
__device__ float         g_zxF[(size_t)TT * 20 * 32 * 16384]; // fragment-order zx (1.80 GB)
__device__ float         g_bias2560[MROWS];
__device__ __nv_bfloat16 g_WHh[(size_t)2 * NDR * KH];        // W_hh hi [d][row'][k]
__device__ __nv_bfloat16 g_WHl[(size_t)2 * NDR * KH];
__device__ __nv_bfloat16 g_Hh[(size_t)2 * 2 * BSZ * KH];     // [buf][d][b][k]
__device__ __nv_bfloat16 g_Hl[(size_t)2 * 2 * BSZ * KH];
__device__ float         g_cF[(size_t)2 * 10 * 32 * 4096];   // fragment-order c
__device__ float         g_hs2[(size_t)BSZ * TT * 2 * KH];   // [b][t][d*320+u]

// ---------------- helpers -------------------------------------------------------
__device__ __forceinline__ float fsig(float x) {
    return __fdividef(1.0f, 1.0f + __expf(-x));
}
__device__ __forceinline__ float ftanh_(float x) {
    float e = __expf(2.0f * x);
    return 1.0f - __fdividef(2.0f, e + 1.0f);
}
__device__ __forceinline__ uint32_t smem_u32(const void* p) {
    uint32_t a;
    asm("{ .reg .u64 t; cvta.to.shared.u64 t, %1; cvt.u32.u64 %0, t; }" : "=r"(a) : "l"(p));
    return a;
}
__device__ __forceinline__ void mma16816(float* c, const uint32_t* a, const uint32_t* b) {
    asm volatile(
        "mma.sync.aligned.m16n8k16.row.col.f32.bf16.bf16.f32 "
        "{%0,%1,%2,%3}, {%4,%5,%6,%7}, {%8,%9}, {%0,%1,%2,%3};"
        : "+f"(c[0]), "+f"(c[1]), "+f"(c[2]), "+f"(c[3])
        : "r"(a[0]), "r"(a[1]), "r"(a[2]), "r"(a[3]), "r"(b[0]), "r"(b[1]));
}
#define LDSM4(r0, r1, r2, r3, addr)                                               \
    asm volatile("ldmatrix.sync.aligned.m8n8.x4.shared.b16 {%0,%1,%2,%3}, [%4];"  \
                 : "=r"(r0), "=r"(r1), "=r"(r2), "=r"(r3) : "r"(addr))

// ---------------- prep kernels --------------------------------------------------
// W_ih, gate-interleaved rows: row' = d*1280 + u*4 + gate
__global__ void prep_wsplit_kernel(const float* __restrict__ wih) {
    int idx = blockIdx.x * blockDim.x + threadIdx.x;
    if (idx >= MROWS * KDIM) return;
    int row = idx / KDIM, k = idx % KDIM;
    int d = row / NDR, r = row % NDR;
    int u = r >> 2, gate = r & 3;
    float v = 0.f;
    if (u < 300 && k < 300)
        v = wih[((size_t)d * 1200 + gate * 300 + u) * 300 + k];
    __nv_bfloat16 hi = __float2bfloat16(v);
    g_Wh[idx] = hi;
    g_Wl[idx] = __float2bfloat16(v - __bfloat162float(hi));
}

__global__ void prep_whhsplit_kernel(const float* __restrict__ whh) {
    int idx = blockIdx.x * blockDim.x + threadIdx.x;
    if (idx >= 2 * NDR * KH) return;
    int row = idx / KH, k = idx % KH;
    int d = row / NDR, r = row % NDR;
    int u = r >> 2, gate = r & 3;
    float v = 0.f;
    if (u < 300 && k < 300)
        v = whh[((size_t)d * 1200 + gate * 300 + u) * 300 + k];
    __nv_bfloat16 hi = __float2bfloat16(v);
    g_WHh[idx] = hi;
    g_WHl[idx] = __float2bfloat16(v - __bfloat162float(hi));
}

// X split via per-batch smem transpose. Block = one batch row b.
#define XS_BYTES (300 * 43 * 4)
__global__ void prep_xsplit_kernel(const float* __restrict__ x) {
    extern __shared__ float xs[];   // [300][43]
    const int b = blockIdx.x;
    const int tid = threadIdx.x;
    for (int i = tid; i < 300 * TT; i += 256) xs[i] = x[(size_t)b * (300 * TT) + i];
    __syncthreads();
    for (int i = tid; i < TT * KDIM; i += 256) {
        int t = i / KDIM, k = i - t * KDIM;
        float v = (k < 300) ? xs[k * TT + t] : 0.f;
        __nv_bfloat16 hi = __float2bfloat16(v);
        size_t o = ((size_t)t * BSZ + b) * KDIM + k;
        g_Xh[o] = hi;
        g_Xl[o] = __float2bfloat16(v - __bfloat162float(hi));
    }
}

__global__ void prep_bias_kernel(const float* __restrict__ bih, const float* __restrict__ bhh) {
    int row = blockIdx.x * blockDim.x + threadIdx.x;
    if (row >= MROWS) return;
    int d = row / NDR, r = row % NDR;
    int u = r >> 2, gate = r & 3;
    float v = 0.f;
    if (u < 300)
        v = bih[(size_t)d * 1200 + gate * 300 + u] + bhh[(size_t)d * 1200 + gate * 300 + u];
    g_bias2560[row] = v;
}

__global__ void zero_state_kernel() {
    size_t i = (size_t)blockIdx.x * blockDim.x + threadIdx.x;
    size_t n = (size_t)2 * BSZ * KH;   // == 2*10*32*4096
    if (i >= n) return;
    g_cF[i] = 0.f;
    g_Hh[i] = __float2bfloat16(0.f);
    g_Hl[i] = __float2bfloat16(0.f);
}

// ---------------- x-precompute GEMM (fragment-order output) ---------------------
#define GS_BYTES 73728
#define TROWB 144

__global__ __launch_bounds__(256, 2)
void gemm_zx_kernel() {
    extern __shared__ char sm[];
    char* Ah = sm;
    char* Al = sm + 18432;
    char* Bh = sm + 36864;
    char* Bl = sm + 55296;
    const int tid  = threadIdx.x;
    const int lane = tid & 31;
    const int wid  = tid >> 5;
    const int wm   = wid & 1;
    const int wn   = wid >> 1;
    const int m0   = blockIdx.x * 128;
    const int n0   = blockIdx.y * 128;

    const uint32_t aRowByte =
        (uint32_t)(wm * 64 + ((lane >> 3) & 1) * 8 + (lane & 7)) * TROWB + (lane >> 4) * 16;
    const uint32_t bRowByte =
        (uint32_t)(wn * 32 + (lane >> 4) * 8 + (lane & 7)) * TROWB + ((lane >> 3) & 1) * 16;
    const uint32_t baseAh = smem_u32(Ah), baseAl = smem_u32(Al);
    const uint32_t baseBh = smem_u32(Bh), baseBl = smem_u32(Bl);

    float acc[4][4][4];
    #pragma unroll
    for (int mt = 0; mt < 4; mt++)
        #pragma unroll
        for (int nt = 0; nt < 4; nt++)
            #pragma unroll
            for (int i = 0; i < 4; i++) acc[mt][nt][i] = 0.f;

    for (int chunk = 0; chunk < 5; chunk++) {
        const int kc0 = chunk * 64;
        __syncthreads();
        for (int i = tid; i < 1024; i += 256) {
            int r = i >> 3, c8 = i & 7;
            uint32_t off = (uint32_t)r * TROWB + c8 * 16;
            size_t sa = (size_t)(m0 + r) * KDIM + kc0 + c8 * 8;
            size_t sb = (size_t)(n0 + r) * KDIM + kc0 + c8 * 8;
            *(uint4*)(Ah + off) = *(const uint4*)(g_Wh + sa);
            *(uint4*)(Al + off) = *(const uint4*)(g_Wl + sa);
            *(uint4*)(Bh + off) = *(const uint4*)(g_Xh + sb);
            *(uint4*)(Bl + off) = *(const uint4*)(g_Xl + sb);
        }
        __syncthreads();

        #pragma unroll
        for (int ks = 0; ks < 4; ks++) {
            const uint32_t kbb = ks * 32;
            uint32_t aF[4][4], bHF[4][2], bLF[4][2];
            #pragma unroll
            for (int mt = 0; mt < 4; mt++)
                LDSM4(aF[mt][0], aF[mt][1], aF[mt][2], aF[mt][3],
                      baseAh + aRowByte + mt * (16 * TROWB) + kbb);
            #pragma unroll
            for (int p = 0; p < 2; p++)
                LDSM4(bHF[2 * p][0], bHF[2 * p][1], bHF[2 * p + 1][0], bHF[2 * p + 1][1],
                      baseBh + bRowByte + p * (16 * TROWB) + kbb);
            #pragma unroll
            for (int p = 0; p < 2; p++)
                LDSM4(bLF[2 * p][0], bLF[2 * p][1], bLF[2 * p + 1][0], bLF[2 * p + 1][1],
                      baseBl + bRowByte + p * (16 * TROWB) + kbb);
            #pragma unroll
            for (int mt = 0; mt < 4; mt++)
                #pragma unroll
                for (int nt = 0; nt < 4; nt++)
                    mma16816(acc[mt][nt], aF[mt], bHF[nt]);
            #pragma unroll
            for (int mt = 0; mt < 4; mt++)
                #pragma unroll
                for (int nt = 0; nt < 4; nt++)
                    mma16816(acc[mt][nt], aF[mt], bLF[nt]);
            #pragma unroll
            for (int mt = 0; mt < 4; mt++)
                LDSM4(aF[mt][0], aF[mt][1], aF[mt][2], aF[mt][3],
                      baseAl + aRowByte + mt * (16 * TROWB) + kbb);
            #pragma unroll
            for (int mt = 0; mt < 4; mt++)
                #pragma unroll
                for (int nt = 0; nt < 4; nt++)
                    mma16816(acc[mt][nt], aF[mt], bHF[nt]);
        }
    }

    // fragment-order store (+bias), coalesced STG.128
    const int t     = blockIdx.y >> 5;
    const int btile = blockIdx.y & 31;
    float4* zf = (float4*)(g_zxF + (((size_t)t * 20 + blockIdx.x) * 32 + btile) * 16384);
    const int rbase = m0 + wm * 64 + (lane >> 2);
    #pragma unroll
    for (int mt = 0; mt < 4; mt++) {
        int row = rbase + mt * 16;
        float br0 = g_bias2560[row];
        float br8 = g_bias2560[row + 8];
        #pragma unroll
        for (int nt = 0; nt < 4; nt++) {
            float4 v = make_float4(acc[mt][nt][0] + br0, acc[mt][nt][1] + br0,
                                   acc[mt][nt][2] + br8, acc[mt][nt][3] + br8);
            zf[(mt * 4 + nt) * 256 + tid] = v;
        }
    }
}

// ---------------- per-step recurrent GEMM (m=rows, n=batch) ---------------------
__global__ __launch_bounds__(256, 2)
void step_kernel(int t) {
    extern __shared__ char sm[];
    char* Ah = sm;
    char* Al = sm + 18432;
    char* Bh = sm + 36864;
    char* Bl = sm + 55296;
    const int tid  = threadIdx.x;
    const int lane = tid & 31;
    const int wid  = tid >> 5;
    const int wm   = wid & 1;
    const int wn   = wid >> 1;
    const int mtl   = blockIdx.x;          // 0..9 row tile within dir
    const int btile = blockIdx.y;          // 0..31 batch tile
    const int d     = blockIdx.z;
    const int m0r   = mtl * 128;
    const int n0b   = btile * 128;
    const int p     = t & 1;
    const int q     = 1 - p;

    const __nv_bfloat16* WhB = g_WHh + (size_t)d * NDR * KH;
    const __nv_bfloat16* WlB = g_WHl + (size_t)d * NDR * KH;
    const __nv_bfloat16* HhB = g_Hh + (size_t)(p * 2 + d) * BSZ * KH;
    const __nv_bfloat16* HlB = g_Hl + (size_t)(p * 2 + d) * BSZ * KH;

    const uint32_t aRowByte =
        (uint32_t)(wm * 64 + ((lane >> 3) & 1) * 8 + (lane & 7)) * TROWB + (lane >> 4) * 16;
    const uint32_t bRowByte =
        (uint32_t)(wn * 32 + (lane >> 4) * 8 + (lane & 7)) * TROWB + ((lane >> 3) & 1) * 16;
    const uint32_t baseAh = smem_u32(Ah), baseAl = smem_u32(Al);
    const uint32_t baseBh = smem_u32(Bh), baseBl = smem_u32(Bl);

    // init acc from fragment-order zx (coalesced LDG.128)
    float acc[4][4][4];
    {
        const float4* zf = (const float4*)(g_zxF +
            (((size_t)t * 20 + (d * 10 + mtl)) * 32 + btile) * 16384);
        #pragma unroll
        for (int mt = 0; mt < 4; mt++)
            #pragma unroll
            for (int nt = 0; nt < 4; nt++) {
                float4 v = zf[(mt * 4 + nt) * 256 + tid];
                acc[mt][nt][0] = v.x; acc[mt][nt][1] = v.y;
                acc[mt][nt][2] = v.z; acc[mt][nt][3] = v.w;
            }
    }

    for (int chunk = 0; chunk < 5; chunk++) {
        const int kc0 = chunk * 64;
        __syncthreads();
        for (int i = tid; i < 1024; i += 256) {
            int r = i >> 3, c8 = i & 7;
            uint32_t off = (uint32_t)r * TROWB + c8 * 16;
            size_t sa = (size_t)(m0r + r) * KH + kc0 + c8 * 8;
            size_t sb = (size_t)(n0b + r) * KH + kc0 + c8 * 8;
            *(uint4*)(Ah + off) = *(const uint4*)(WhB + sa);
            *(uint4*)(Al + off) = *(const uint4*)(WlB + sa);
            *(uint4*)(Bh + off) = *(const uint4*)(HhB + sb);
            *(uint4*)(Bl + off) = *(const uint4*)(HlB + sb);
        }
        __syncthreads();

        #pragma unroll
        for (int ks = 0; ks < 4; ks++) {
            const uint32_t kbb = ks * 32;
            uint32_t aF[4][4], bHF[4][2], bLF[4][2];
            #pragma unroll
            for (int mt = 0; mt < 4; mt++)
                LDSM4(aF[mt][0], aF[mt][1], aF[mt][2], aF[mt][3],
                      baseAh + aRowByte + mt * (16 * TROWB) + kbb);
            #pragma unroll
            for (int pp = 0; pp < 2; pp++)
                LDSM4(bHF[2 * pp][0], bHF[2 * pp][1], bHF[2 * pp + 1][0], bHF[2 * pp + 1][1],
                      baseBh + bRowByte + pp * (16 * TROWB) + kbb);
            #pragma unroll
            for (int pp = 0; pp < 2; pp++)
                LDSM4(bLF[2 * pp][0], bLF[2 * pp][1], bLF[2 * pp + 1][0], bLF[2 * pp + 1][1],
                      baseBl + bRowByte + pp * (16 * TROWB) + kbb);
            #pragma unroll
            for (int mt = 0; mt < 4; mt++)
                #pragma unroll
                for (int nt = 0; nt < 4; nt++)
                    mma16816(acc[mt][nt], aF[mt], bHF[nt]);
            #pragma unroll
            for (int mt = 0; mt < 4; mt++)
                #pragma unroll
                for (int nt = 0; nt < 4; nt++)
                    mma16816(acc[mt][nt], aF[mt], bLF[nt]);
            #pragma unroll
            for (int mt = 0; mt < 4; mt++)
                LDSM4(aF[mt][0], aF[mt][1], aF[mt][2], aF[mt][3],
                      baseAl + aRowByte + mt * (16 * TROWB) + kbb);
            #pragma unroll
            for (int mt = 0; mt < 4; mt++)
                #pragma unroll
                for (int nt = 0; nt < 4; nt++)
                    mma16816(acc[mt][nt], aF[mt], bHF[nt]);
        }
    }
    __syncthreads();   // smem reuse below

    // ---- epilogue: 4-lane fragment transpose -> gates -> c update -> hT ----
    const int g = (lane >> 2) & 3;      // this lane's gate index (and element selector)
    float* cS = g_cF + ((size_t)(d * 10 + mtl) * 32 + btile) * 4096;
    float* hT = (float*)sm;             // [128 batch][33] padded

    #pragma unroll
    for (int mt = 0; mt < 4; mt++) {
        #pragma unroll
        for (int nt = 0; nt < 4; nt++) {
            float v0 = acc[mt][nt][0], v1 = acc[mt][nt][1];
            float v2 = acc[mt][nt][2], v3 = acc[mt][nt][3];
            // round 1 (xor 8): move 2x2 blocks
            float a = (g & 2) ? v0 : v2;
            float b = (g & 2) ? v1 : v3;
            a = __shfl_xor_sync(0xffffffffu, a, 8);
            b = __shfl_xor_sync(0xffffffffu, b, 8);
            if (g & 2) { v0 = a; v1 = b; } else { v2 = a; v3 = b; }
            // round 2 (xor 4): transpose within 2x2 blocks
            float c01 = (g & 1) ? v0 : v1;
            c01 = __shfl_xor_sync(0xffffffffu, c01, 4);
            if (g & 1) v0 = c01; else v1 = c01;
            float c23 = (g & 1) ? v2 : v3;
            c23 = __shfl_xor_sync(0xffffffffu, c23, 4);
            if (g & 1) v2 = c23; else v3 = c23;
            // v0..v3 = (z_i, z_f, z_g, z_o) at fragment element index g
            size_t ci = (size_t)(mt * 4 + nt) * 256 + tid;
            float co = cS[ci];
            float cn = fsig(v1) * co + fsig(v0) * ftanh_(v2);
            cS[ci] = cn;
            float h = fsig(v3) * ftanh_(cn);
            int U = wm * 16 + mt * 4 + ((lane >> 4) & 1) + 2 * (g >> 1);
            int N = wn * 32 + nt * 8 + (lane & 3) * 2 + (g & 1);
            hT[N * 33 + U] = h;
        }
    }
    __syncthreads();

    // coalesced write-out: Hh/Hl (next-step operand) + hs2 (attention)
    __nv_bfloat16* HhO = g_Hh + (size_t)(q * 2 + d) * BSZ * KH;
    __nv_bfloat16* HlO = g_Hl + (size_t)(q * 2 + d) * BSZ * KH;
    const int U0 = mtl * 32;
    for (int i = tid; i < 128 * 32; i += 256) {
        int bl = i >> 5, ul = i & 31;
        float h = hT[bl * 33 + ul];
        int b = n0b + bl;
        int u = U0 + ul;
        size_t hi = (size_t)b * KH + u;
        __nv_bfloat16 hh = __float2bfloat16(h);
        HhO[hi] = hh;
        HlO[hi] = __float2bfloat16(h - __bfloat162float(hh));
        g_hs2[((size_t)b * TT + t) * (2 * KH) + d * KH + u] = h;
    }
}

// ---------------- attention + FC epilogue ---------------------------------------
#define ATT_SMEM 119856

__global__ __launch_bounds__(256, 1)
void attn_kernel(const float* __restrict__ conv_w,
                 const float* __restrict__ fc_w,
                 const float* __restrict__ fc_b,
                 float* __restrict__ out) {
    extern __shared__ char smem[];
    float* fcT   = (float*)smem;               // [300][80]
    float* hstar = (float*)(smem + 96000);     // [16][300]
    float* cw    = (float*)(smem + 115200);    // [300]
    float* e_sh  = cw + 300;                   // [16][44]
    float* l_sh  = e_sh + 704;                 // [80]
    float* p_sh  = l_sh + 80;                  // [80]

    const int tid = threadIdx.x;
    const int b0  = blockIdx.x * 16;

    for (int i = tid; i < 300; i += 256) cw[i] = conv_w[i];
    for (int i = tid; i < 300 * NCLS; i += 256) {
        int u = i / NCLS, cls = i - u * NCLS;
        fcT[i] = fc_w[(size_t)cls * 300 + u];
    }
    __syncthreads();

    {
        int wid = tid >> 5, lane = tid & 31;
        for (int task = wid; task < 16 * TT; task += 8) {
            int b = task / TT, t = task - b * TT;
            const float* hp = g_hs2 + ((size_t)(b0 + b) * TT + t) * (2 * KH);
            float s = 0.f;
            for (int u = lane; u < 300; u += 32)
                s += ftanh_(hp[u] + hp[KH + u]) * cw[u];
            #pragma unroll
            for (int o = 16; o > 0; o >>= 1) s += __shfl_xor_sync(0xffffffffu, s, o);
            if (lane == 0) e_sh[b * 44 + t] = s;
        }
    }
    __syncthreads();

    if (tid < 16) {
        float m = -1e30f;
        for (int t = 0; t < TT; t++) m = fmaxf(m, e_sh[tid * 44 + t]);
        float ss = 0.f;
        for (int t = 0; t < TT; t++) { float pz = __expf(e_sh[tid * 44 + t] - m); e_sh[tid * 44 + t] = pz; ss += pz; }
        float inv = 1.0f / ss;
        for (int t = 0; t < TT; t++) e_sh[tid * 44 + t] *= inv;
    }
    __syncthreads();

    for (int i = tid; i < 16 * 300; i += 256) {
        int b = i / 300, u = i - b * 300;
        const float* hp = g_hs2 + ((size_t)(b0 + b) * TT) * (2 * KH) + u;
        float acc = 0.f;
        for (int t = 0; t < TT; t++)
            acc += (hp[(size_t)t * (2 * KH)] + hp[(size_t)t * (2 * KH) + KH]) * e_sh[b * 44 + t];
        hstar[i] = ftanh_(acc);
    }
    __syncthreads();

    for (int b = 0; b < 16; b++) {
        if (tid < NCLS) {
            float acc = fc_b[tid];
            const float* hv = hstar + b * 300;
            for (int u = 0; u < 300; u++) acc += hv[u] * fcT[u * NCLS + tid];
            l_sh[tid] = acc;
        }
        __syncthreads();
        if (tid < NCLS) {
            float m = -1e30f;
            for (int j = 0; j < NCLS; j++) m = fmaxf(m, l_sh[j]);
            p_sh[tid] = __expf(l_sh[tid] - m);
        }
        __syncthreads();
        if (tid < NCLS) {
            float s = 0.f;
            for (int j = 0; j < NCLS; j++) s += p_sh[j];
            out[(size_t)(b0 + b) * NCLS + tid] = p_sh[tid] / s;
        }
        __syncthreads();
    }
}

// ---------------- launch ---------------------------------------------------------
extern "C" void kernel_launch(void* const* d_in, const int* in_sizes, int n_in,
                              void* d_out, int out_size) {
    const float* x      = (const float*)d_in[0];
    const float* w_ih   = (const float*)d_in[1];
    const float* w_hh   = (const float*)d_in[2];
    const float* b_ih   = (const float*)d_in[3];
    const float* b_hh   = (const float*)d_in[4];
    const float* conv_w = (const float*)d_in[5];
    const float* fc_w   = (const float*)d_in[6];
    const float* fc_b   = (const float*)d_in[7];
    float* out = (float*)d_out;

    cudaFuncSetAttribute(gemm_zx_kernel,   cudaFuncAttributeMaxDynamicSharedMemorySize, GS_BYTES);
    cudaFuncSetAttribute(step_kernel,      cudaFuncAttributeMaxDynamicSharedMemorySize, GS_BYTES);
    cudaFuncSetAttribute(attn_kernel,      cudaFuncAttributeMaxDynamicSharedMemorySize, ATT_SMEM);
    cudaFuncSetAttribute(prep_xsplit_kernel, cudaFuncAttributeMaxDynamicSharedMemorySize, XS_BYTES);

    prep_wsplit_kernel<<<(MROWS * KDIM + 255) / 256, 256>>>(w_ih);
    prep_whhsplit_kernel<<<(2 * NDR * KH + 255) / 256, 256>>>(w_hh);
    prep_xsplit_kernel<<<BSZ, 256, XS_BYTES>>>(x);
    prep_bias_kernel<<<(MROWS + 255) / 256, 256>>>(b_ih, b_hh);
    zero_state_kernel<<<(int)(((size_t)2 * BSZ * KH + 255) / 256), 256>>>();

    gemm_zx_kernel<<<dim3(MTILES, NTILES), 256, GS_BYTES>>>();

    for (int t = 0; t < TT; t++)
        step_kernel<<<dim3(10, 32, 2), 256, GS_BYTES>>>(t);

    attn_kernel<<<BSZ / 16, 256, ATT_SMEM>>>(conv_w, fc_w, fc_b, out);
}

// round 9
// speedup vs baseline: 2.1901x; 1.0304x over previous
#include <cuda_runtime.h>
#include <cuda_bf16.h>
#include <math.h>
#include <stdint.h>

// Problem constants
#define BSZ   4096
#define HDIM  300
#define TT    43
#define NCLS  80

// GEMM shapes (x-precompute): m = 2560 weight rows, n = 176128 (t,b) cols
#define MROWS 2560
#define KDIM  320
#define NCOLS 176128
#define MTILES 20
#define NTILES 1376
// recurrence
#define NDR   1280
#define KH    320

// pipeline staging
#define KC2    32
#define NCH    10          // 320/32
#define TRB    80          // bytes per 32-k row (64 data + 16 pad)
#define TILEB  10240       // 128 * TRB
#define STAGEB 40960       // 4 tiles
#define GS_BYTES (2 * STAGEB)   // 81920

// ---------------- device scratch ----------------------------------------------
__device__ __nv_bfloat16 g_Wh[(size_t)MROWS * KDIM];
__device__ __nv_bfloat16 g_Wl[(size_t)MROWS * KDIM];
__device__ __nv_bfloat16 g_Xh[(size_t)NCOLS * KDIM];
__device__ __nv_bfloat16 g_Xl[(size_t)NCOLS * KDIM];
__device__ float         g_zxF[(size_t)TT * 20 * 32 * 16384]; // fragment-order zx
__device__ float         g_bias2560[MROWS];
__device__ __nv_bfloat16 g_WHh[(size_t)2 * NDR * KH];
__device__ __nv_bfloat16 g_WHl[(size_t)2 * NDR * KH];
__device__ __nv_bfloat16 g_Hh[(size_t)2 * 2 * BSZ * KH];
__device__ __nv_bfloat16 g_Hl[(size_t)2 * 2 * BSZ * KH];
__device__ float         g_cF[(size_t)2 * 10 * 32 * 4096];
__device__ float         g_hs2[(size_t)BSZ * TT * 2 * KH];

// ---------------- helpers -------------------------------------------------------
__device__ __forceinline__ float fsig(float x) {
    return __fdividef(1.0f, 1.0f + __expf(-x));
}
__device__ __forceinline__ float ftanh_(float x) {
    float e = __expf(2.0f * x);
    return 1.0f - __fdividef(2.0f, e + 1.0f);
}
__device__ __forceinline__ uint32_t smem_u32(const void* p) {
    uint32_t a;
    asm("{ .reg .u64 t; cvta.to.shared.u64 t, %1; cvt.u32.u64 %0, t; }" : "=r"(a) : "l"(p));
    return a;
}
__device__ __forceinline__ void mma16816(float* c, const uint32_t* a, const uint32_t* b) {
    asm volatile(
        "mma.sync.aligned.m16n8k16.row.col.f32.bf16.bf16.f32 "
        "{%0,%1,%2,%3}, {%4,%5,%6,%7}, {%8,%9}, {%0,%1,%2,%3};"
        : "+f"(c[0]), "+f"(c[1]), "+f"(c[2]), "+f"(c[3])
        : "r"(a[0]), "r"(a[1]), "r"(a[2]), "r"(a[3]), "r"(b[0]), "r"(b[1]));
}
#define LDSM4(r0, r1, r2, r3, addr)                                               \
    asm volatile("ldmatrix.sync.aligned.m8n8.x4.shared.b16 {%0,%1,%2,%3}, [%4];"  \
                 : "=r"(r0), "=r"(r1), "=r"(r2), "=r"(r3) : "r"(addr))
#define CPA16(dst, src)                                                           \
    asm volatile("cp.async.cg.shared.global [%0], [%1], 16;" :: "r"(dst), "l"(src))
#define CPA_COMMIT() asm volatile("cp.async.commit_group;")
#define CPA_WAIT1()  asm volatile("cp.async.wait_group 1;")
#define CPA_WAIT0()  asm volatile("cp.async.wait_group 0;")

// ---------------- prep kernels --------------------------------------------------
__global__ void prep_wsplit_kernel(const float* __restrict__ wih) {
    int idx = blockIdx.x * blockDim.x + threadIdx.x;
    if (idx >= MROWS * KDIM) return;
    int row = idx / KDIM, k = idx % KDIM;
    int d = row / NDR, r = row % NDR;
    int u = r >> 2, gate = r & 3;
    float v = 0.f;
    if (u < 300 && k < 300)
        v = wih[((size_t)d * 1200 + gate * 300 + u) * 300 + k];
    __nv_bfloat16 hi = __float2bfloat16(v);
    g_Wh[idx] = hi;
    g_Wl[idx] = __float2bfloat16(v - __bfloat162float(hi));
}

__global__ void prep_whhsplit_kernel(const float* __restrict__ whh) {
    int idx = blockIdx.x * blockDim.x + threadIdx.x;
    if (idx >= 2 * NDR * KH) return;
    int row = idx / KH, k = idx % KH;
    int d = row / NDR, r = row % NDR;
    int u = r >> 2, gate = r & 3;
    float v = 0.f;
    if (u < 300 && k < 300)
        v = whh[((size_t)d * 1200 + gate * 300 + u) * 300 + k];
    __nv_bfloat16 hi = __float2bfloat16(v);
    g_WHh[idx] = hi;
    g_WHl[idx] = __float2bfloat16(v - __bfloat162float(hi));
}

#define XS_BYTES (300 * 43 * 4)
__global__ void prep_xsplit_kernel(const float* __restrict__ x) {
    extern __shared__ float xs[];
    const int b = blockIdx.x;
    const int tid = threadIdx.x;
    for (int i = tid; i < 300 * TT; i += 256) xs[i] = x[(size_t)b * (300 * TT) + i];
    __syncthreads();
    for (int i = tid; i < TT * KDIM; i += 256) {
        int t = i / KDIM, k = i - t * KDIM;
        float v = (k < 300) ? xs[k * TT + t] : 0.f;
        __nv_bfloat16 hi = __float2bfloat16(v);
        size_t o = ((size_t)t * BSZ + b) * KDIM + k;
        g_Xh[o] = hi;
        g_Xl[o] = __float2bfloat16(v - __bfloat162float(hi));
    }
}

__global__ void prep_bias_kernel(const float* __restrict__ bih, const float* __restrict__ bhh) {
    int row = blockIdx.x * blockDim.x + threadIdx.x;
    if (row >= MROWS) return;
    int d = row / NDR, r = row % NDR;
    int u = r >> 2, gate = r & 3;
    float v = 0.f;
    if (u < 300)
        v = bih[(size_t)d * 1200 + gate * 300 + u] + bhh[(size_t)d * 1200 + gate * 300 + u];
    g_bias2560[row] = v;
}

__global__ void zero_state_kernel() {
    size_t i = (size_t)blockIdx.x * blockDim.x + threadIdx.x;
    size_t n = (size_t)2 * BSZ * KH;
    if (i >= n) return;
    g_cF[i] = 0.f;
    g_Hh[i] = __float2bfloat16(0.f);
    g_Hl[i] = __float2bfloat16(0.f);
}

// ---------------- staging + MMA core (shared between the two GEMM kernels) ------
// Stage layout within a stage: Ah @0, Al @TILEB, Bh @2*TILEB, Bl @3*TILEB.
// Per stage-load: 2048 x 16B chunks; it>>1 = tile (compile-time per unroll iter).
#define STAGE_LOAD(ss, kc0, Asrc_h, Asrc_l, Bsrc_h, Bsrc_l, aRow0, bRow0, aStride, bStride) \
    {                                                                                       \
        uint32_t _sb = smb + (ss) * STAGEB;                                                 \
        _Pragma("unroll")                                                                   \
        for (int it = 0; it < 8; it++) {                                                    \
            int j = ((it & 1) << 8) + tid;                                                  \
            int r = j >> 2, c4 = j & 3;                                                     \
            uint32_t dst = _sb + (it >> 1) * TILEB + r * TRB + c4 * 16;                     \
            const __nv_bfloat16* src;                                                       \
            if ((it >> 1) == 0)      src = (Asrc_h) + (size_t)((aRow0) + r) * (aStride) + (kc0) + c4 * 8; \
            else if ((it >> 1) == 1) src = (Asrc_l) + (size_t)((aRow0) + r) * (aStride) + (kc0) + c4 * 8; \
            else if ((it >> 1) == 2) src = (Bsrc_h) + (size_t)((bRow0) + r) * (bStride) + (kc0) + c4 * 8; \
            else                     src = (Bsrc_l) + (size_t)((bRow0) + r) * (bStride) + (kc0) + c4 * 8; \
            CPA16(dst, src);                                                                \
        }                                                                                   \
        CPA_COMMIT();                                                                       \
    }

#define MMA_CHUNK(ss)                                                                       \
    {                                                                                       \
        uint32_t _sb = smb + (ss) * STAGEB;                                                 \
        uint32_t bAh = _sb, bAl = _sb + TILEB, bBh = _sb + 2 * TILEB, bBl = _sb + 3 * TILEB;\
        _Pragma("unroll")                                                                   \
        for (int ks = 0; ks < 2; ks++) {                                                    \
            const uint32_t kbb = ks * 32;                                                   \
            uint32_t aF[4][4], bHF[4][2], bLF[4][2];                                        \
            _Pragma("unroll")                                                               \
            for (int mt = 0; mt < 4; mt++)                                                  \
                LDSM4(aF[mt][0], aF[mt][1], aF[mt][2], aF[mt][3],                           \
                      bAh + aRowByte + mt * (16 * TRB) + kbb);                              \
            _Pragma("unroll")                                                               \
            for (int pp = 0; pp < 2; pp++)                                                  \
                LDSM4(bHF[2 * pp][0], bHF[2 * pp][1], bHF[2 * pp + 1][0], bHF[2 * pp + 1][1],\
                      bBh + bRowByte + pp * (16 * TRB) + kbb);                              \
            _Pragma("unroll")                                                               \
            for (int pp = 0; pp < 2; pp++)                                                  \
                LDSM4(bLF[2 * pp][0], bLF[2 * pp][1], bLF[2 * pp + 1][0], bLF[2 * pp + 1][1],\
                      bBl + bRowByte + pp * (16 * TRB) + kbb);                              \
            _Pragma("unroll")                                                               \
            for (int mt = 0; mt < 4; mt++)                                                  \
                _Pragma("unroll")                                                           \
                for (int nt = 0; nt < 4; nt++)                                              \
                    mma16816(acc[mt][nt], aF[mt], bHF[nt]);                                 \
            _Pragma("unroll")                                                               \
            for (int mt = 0; mt < 4; mt++)                                                  \
                _Pragma("unroll")                                                           \
                for (int nt = 0; nt < 4; nt++)                                              \
                    mma16816(acc[mt][nt], aF[mt], bLF[nt]);                                 \
            _Pragma("unroll")                                                               \
            for (int mt = 0; mt < 4; mt++)                                                  \
                LDSM4(aF[mt][0], aF[mt][1], aF[mt][2], aF[mt][3],                           \
                      bAl + aRowByte + mt * (16 * TRB) + kbb);                              \
            _Pragma("unroll")                                                               \
            for (int mt = 0; mt < 4; mt++)                                                  \
                _Pragma("unroll")                                                           \
                for (int nt = 0; nt < 4; nt++)                                              \
                    mma16816(acc[mt][nt], aF[mt], bHF[nt]);                                 \
        }                                                                                   \
    }

// ---------------- x-precompute GEMM (fragment-order output) ---------------------
__global__ __launch_bounds__(256, 2)
void gemm_zx_kernel() {
    extern __shared__ char sm[];
    const uint32_t smb = smem_u32(sm);
    const int tid  = threadIdx.x;
    const int lane = tid & 31;
    const int wid  = tid >> 5;
    const int wm   = wid & 1;
    const int wn   = wid >> 1;
    const int m0   = blockIdx.x * 128;
    const int n0   = blockIdx.y * 128;

    const uint32_t aRowByte =
        (uint32_t)(wm * 64 + ((lane >> 3) & 1) * 8 + (lane & 7)) * TRB + (lane >> 4) * 16;
    const uint32_t bRowByte =
        (uint32_t)(wn * 32 + (lane >> 4) * 8 + (lane & 7)) * TRB + ((lane >> 3) & 1) * 16;

    float acc[4][4][4];
    #pragma unroll
    for (int mt = 0; mt < 4; mt++)
        #pragma unroll
        for (int nt = 0; nt < 4; nt++)
            #pragma unroll
            for (int i = 0; i < 4; i++) acc[mt][nt][i] = 0.f;

    STAGE_LOAD(0, 0, g_Wh, g_Wl, g_Xh, g_Xl, m0, n0, KDIM, KDIM);
    for (int chunk = 0; chunk < NCH; chunk++) {
        const int ss = chunk & 1;
        if (chunk + 1 < NCH) {
            STAGE_LOAD(ss ^ 1, (chunk + 1) * KC2, g_Wh, g_Wl, g_Xh, g_Xl, m0, n0, KDIM, KDIM);
            CPA_WAIT1();
        } else {
            CPA_WAIT0();
        }
        __syncthreads();
        MMA_CHUNK(ss);
        __syncthreads();
    }

    // fragment-order store (+bias)
    const int t     = blockIdx.y >> 5;
    const int btile = blockIdx.y & 31;
    float4* zf = (float4*)(g_zxF + (((size_t)t * 20 + blockIdx.x) * 32 + btile) * 16384);
    const int rbase = m0 + wm * 64 + (lane >> 2);
    #pragma unroll
    for (int mt = 0; mt < 4; mt++) {
        int row = rbase + mt * 16;
        float br0 = g_bias2560[row];
        float br8 = g_bias2560[row + 8];
        #pragma unroll
        for (int nt = 0; nt < 4; nt++) {
            float4 v = make_float4(acc[mt][nt][0] + br0, acc[mt][nt][1] + br0,
                                   acc[mt][nt][2] + br8, acc[mt][nt][3] + br8);
            zf[(mt * 4 + nt) * 256 + tid] = v;
        }
    }
}

// ---------------- per-step recurrent GEMM (m=rows, n=batch) ---------------------
__global__ __launch_bounds__(256, 2)
void step_kernel(int t) {
    extern __shared__ char sm[];
    const uint32_t smb = smem_u32(sm);
    const int tid  = threadIdx.x;
    const int lane = tid & 31;
    const int wid  = tid >> 5;
    const int wm   = wid & 1;
    const int wn   = wid >> 1;
    const int mtl   = blockIdx.x;
    const int btile = blockIdx.y;
    const int d     = blockIdx.z;
    const int m0r   = mtl * 128;
    const int n0b   = btile * 128;
    const int p     = t & 1;
    const int q     = 1 - p;

    const __nv_bfloat16* WhB = g_WHh + (size_t)d * NDR * KH;
    const __nv_bfloat16* WlB = g_WHl + (size_t)d * NDR * KH;
    const __nv_bfloat16* HhB = g_Hh + (size_t)(p * 2 + d) * BSZ * KH;
    const __nv_bfloat16* HlB = g_Hl + (size_t)(p * 2 + d) * BSZ * KH;

    const uint32_t aRowByte =
        (uint32_t)(wm * 64 + ((lane >> 3) & 1) * 8 + (lane & 7)) * TRB + (lane >> 4) * 16;
    const uint32_t bRowByte =
        (uint32_t)(wn * 32 + (lane >> 4) * 8 + (lane & 7)) * TRB + ((lane >> 3) & 1) * 16;

    STAGE_LOAD(0, 0, WhB, WlB, HhB, HlB, m0r, n0b, KH, KH);

    // init acc from fragment-order zx (overlaps with cp.async staging)
    float acc[4][4][4];
    {
        const float4* zf = (const float4*)(g_zxF +
            (((size_t)t * 20 + (d * 10 + mtl)) * 32 + btile) * 16384);
        #pragma unroll
        for (int mt = 0; mt < 4; mt++)
            #pragma unroll
            for (int nt = 0; nt < 4; nt++) {
                float4 v = zf[(mt * 4 + nt) * 256 + tid];
                acc[mt][nt][0] = v.x; acc[mt][nt][1] = v.y;
                acc[mt][nt][2] = v.z; acc[mt][nt][3] = v.w;
            }
    }

    for (int chunk = 0; chunk < NCH; chunk++) {
        const int ss = chunk & 1;
        if (chunk + 1 < NCH) {
            STAGE_LOAD(ss ^ 1, (chunk + 1) * KC2, WhB, WlB, HhB, HlB, m0r, n0b, KH, KH);
            CPA_WAIT1();
        } else {
            CPA_WAIT0();
        }
        __syncthreads();
        MMA_CHUNK(ss);
        __syncthreads();
    }

    // ---- epilogue: 4-lane fragment transpose -> gates -> c update -> hT ----
    const int g = (lane >> 2) & 3;
    float* cS = g_cF + ((size_t)(d * 10 + mtl) * 32 + btile) * 4096;
    float* hT = (float*)sm;   // [128 batch][33] padded (17 KB, stage area reuse)

    #pragma unroll
    for (int mt = 0; mt < 4; mt++) {
        #pragma unroll
        for (int nt = 0; nt < 4; nt++) {
            float v0 = acc[mt][nt][0], v1 = acc[mt][nt][1];
            float v2 = acc[mt][nt][2], v3 = acc[mt][nt][3];
            float a = (g & 2) ? v0 : v2;
            float b = (g & 2) ? v1 : v3;
            a = __shfl_xor_sync(0xffffffffu, a, 8);
            b = __shfl_xor_sync(0xffffffffu, b, 8);
            if (g & 2) { v0 = a; v1 = b; } else { v2 = a; v3 = b; }
            float c01 = (g & 1) ? v0 : v1;
            c01 = __shfl_xor_sync(0xffffffffu, c01, 4);
            if (g & 1) v0 = c01; else v1 = c01;
            float c23 = (g & 1) ? v2 : v3;
            c23 = __shfl_xor_sync(0xffffffffu, c23, 4);
            if (g & 1) v2 = c23; else v3 = c23;
            size_t ci = (size_t)(mt * 4 + nt) * 256 + tid;
            float co = cS[ci];
            float cn = fsig(v1) * co + fsig(v0) * ftanh_(v2);
            cS[ci] = cn;
            float h = fsig(v3) * ftanh_(cn);
            int U = wm * 16 + mt * 4 + ((lane >> 4) & 1) + 2 * (g >> 1);
            int N = wn * 32 + nt * 8 + (lane & 3) * 2 + (g & 1);
            hT[N * 33 + U] = h;
        }
    }
    __syncthreads();

    __nv_bfloat16* HhO = g_Hh + (size_t)(q * 2 + d) * BSZ * KH;
    __nv_bfloat16* HlO = g_Hl + (size_t)(q * 2 + d) * BSZ * KH;
    const int U0 = mtl * 32;
    for (int i = tid; i < 128 * 32; i += 256) {
        int bl = i >> 5, ul = i & 31;
        float h = hT[bl * 33 + ul];
        int b = n0b + bl;
        int u = U0 + ul;
        size_t hi = (size_t)b * KH + u;
        __nv_bfloat16 hh = __float2bfloat16(h);
        HhO[hi] = hh;
        HlO[hi] = __float2bfloat16(h - __bfloat162float(hh));
        g_hs2[((size_t)b * TT + t) * (2 * KH) + d * KH + u] = h;
    }
}

// ---------------- attention + FC epilogue ---------------------------------------
#define ATT_SMEM 119856

__global__ __launch_bounds__(256, 1)
void attn_kernel(const float* __restrict__ conv_w,
                 const float* __restrict__ fc_w,
                 const float* __restrict__ fc_b,
                 float* __restrict__ out) {
    extern __shared__ char smem[];
    float* fcT   = (float*)smem;
    float* hstar = (float*)(smem + 96000);
    float* cw    = (float*)(smem + 115200);
    float* e_sh  = cw + 300;
    float* l_sh  = e_sh + 704;
    float* p_sh  = l_sh + 80;

    const int tid = threadIdx.x;
    const int b0  = blockIdx.x * 16;

    for (int i = tid; i < 300; i += 256) cw[i] = conv_w[i];
    for (int i = tid; i < 300 * NCLS; i += 256) {
        int u = i / NCLS, cls = i - u * NCLS;
        fcT[i] = fc_w[(size_t)cls * 300 + u];
    }
    __syncthreads();

    {
        int wid = tid >> 5, lane = tid & 31;
        for (int task = wid; task < 16 * TT; task += 8) {
            int b = task / TT, t = task - b * TT;
            const float* hp = g_hs2 + ((size_t)(b0 + b) * TT + t) * (2 * KH);
            float s = 0.f;
            for (int u = lane; u < 300; u += 32)
                s += ftanh_(hp[u] + hp[KH + u]) * cw[u];
            #pragma unroll
            for (int o = 16; o > 0; o >>= 1) s += __shfl_xor_sync(0xffffffffu, s, o);
            if (lane == 0) e_sh[b * 44 + t] = s;
        }
    }
    __syncthreads();

    if (tid < 16) {
        float m = -1e30f;
        for (int t = 0; t < TT; t++) m = fmaxf(m, e_sh[tid * 44 + t]);
        float ss = 0.f;
        for (int t = 0; t < TT; t++) { float pz = __expf(e_sh[tid * 44 + t] - m); e_sh[tid * 44 + t] = pz; ss += pz; }
        float inv = 1.0f / ss;
        for (int t = 0; t < TT; t++) e_sh[tid * 44 + t] *= inv;
    }
    __syncthreads();

    for (int i = tid; i < 16 * 300; i += 256) {
        int b = i / 300, u = i - b * 300;
        const float* hp = g_hs2 + ((size_t)(b0 + b) * TT) * (2 * KH) + u;
        float acc = 0.f;
        for (int t = 0; t < TT; t++)
            acc += (hp[(size_t)t * (2 * KH)] + hp[(size_t)t * (2 * KH) + KH]) * e_sh[b * 44 + t];
        hstar[i] = ftanh_(acc);
    }
    __syncthreads();

    for (int b = 0; b < 16; b++) {
        if (tid < NCLS) {
            float acc = fc_b[tid];
            const float* hv = hstar + b * 300;
            for (int u = 0; u < 300; u++) acc += hv[u] * fcT[u * NCLS + tid];
            l_sh[tid] = acc;
        }
        __syncthreads();
        if (tid < NCLS) {
            float m = -1e30f;
            for (int j = 0; j < NCLS; j++) m = fmaxf(m, l_sh[j]);
            p_sh[tid] = __expf(l_sh[tid] - m);
        }
        __syncthreads();
        if (tid < NCLS) {
            float s = 0.f;
            for (int j = 0; j < NCLS; j++) s += p_sh[j];
            out[(size_t)(b0 + b) * NCLS + tid] = p_sh[tid] / s;
        }
        __syncthreads();
    }
}

// ---------------- launch ---------------------------------------------------------
extern "C" void kernel_launch(void* const* d_in, const int* in_sizes, int n_in,
                              void* d_out, int out_size) {
    const float* x      = (const float*)d_in[0];
    const float* w_ih   = (const float*)d_in[1];
    const float* w_hh   = (const float*)d_in[2];
    const float* b_ih   = (const float*)d_in[3];
    const float* b_hh   = (const float*)d_in[4];
    const float* conv_w = (const float*)d_in[5];
    const float* fc_w   = (const float*)d_in[6];
    const float* fc_b   = (const float*)d_in[7];
    float* out = (float*)d_out;

    cudaFuncSetAttribute(gemm_zx_kernel,     cudaFuncAttributeMaxDynamicSharedMemorySize, GS_BYTES);
    cudaFuncSetAttribute(step_kernel,        cudaFuncAttributeMaxDynamicSharedMemorySize, GS_BYTES);
    cudaFuncSetAttribute(attn_kernel,        cudaFuncAttributeMaxDynamicSharedMemorySize, ATT_SMEM);
    cudaFuncSetAttribute(prep_xsplit_kernel, cudaFuncAttributeMaxDynamicSharedMemorySize, XS_BYTES);

    prep_wsplit_kernel<<<(MROWS * KDIM + 255) / 256, 256>>>(w_ih);
    prep_whhsplit_kernel<<<(2 * NDR * KH + 255) / 256, 256>>>(w_hh);
    prep_xsplit_kernel<<<BSZ, 256, XS_BYTES>>>(x);
    prep_bias_kernel<<<(MROWS + 255) / 256, 256>>>(b_ih, b_hh);
    zero_state_kernel<<<(int)(((size_t)2 * BSZ * KH + 255) / 256), 256>>>();

    gemm_zx_kernel<<<dim3(MTILES, NTILES), 256, GS_BYTES>>>();

    for (int t = 0; t < TT; t++)
        step_kernel<<<dim3(10, 32, 2), 256, GS_BYTES>>>(t);

    attn_kernel<<<BSZ / 16, 256, ATT_SMEM>>>(conv_w, fc_w, fc_b, out);
}

// round 10
// speedup vs baseline: 2.4632x; 1.1247x over previous
#include <cuda_runtime.h>
#include <cuda_bf16.h>
#include <math.h>
#include <stdint.h>

// Problem constants
#define BSZ   4096
#define HDIM  300
#define TT    43
#define NCLS  80

// GEMM shapes (x-precompute): m = 2560 weight rows, n = 4096 batch per t
#define MROWS 2560
#define KDIM  320
#define NCOLS 176128
#define MTILES 20
// recurrence
#define NDR   1280
#define KH    320

// pipeline staging
#define KC2    32
#define NCH    10          // 320/32
#define TRB    80          // bytes per 32-k row (64 data + 16 pad)
#define TILEB  10240       // 128 * TRB
#define STAGEB 40960       // 4 tiles
#define GS_BYTES (2 * STAGEB)   // 81920

// ---------------- device scratch ----------------------------------------------
__device__ __nv_bfloat16 g_Wh[(size_t)MROWS * KDIM];
__device__ __nv_bfloat16 g_Wl[(size_t)MROWS * KDIM];
__device__ __nv_bfloat16 g_Xh[(size_t)NCOLS * KDIM];
__device__ __nv_bfloat16 g_Xl[(size_t)NCOLS * KDIM];
__device__ float         g_zxF[(size_t)TT * 20 * 32 * 16384]; // fragment-order zx
__device__ float         g_bias2560[MROWS];
__device__ __nv_bfloat16 g_WHh[(size_t)2 * NDR * KH];
__device__ __nv_bfloat16 g_WHl[(size_t)2 * NDR * KH];
__device__ __nv_bfloat16 g_Hh[(size_t)2 * 2 * BSZ * KH];
__device__ __nv_bfloat16 g_Hl[(size_t)2 * 2 * BSZ * KH];
__device__ float         g_cF[(size_t)2 * 10 * 32 * 4096];
__device__ float         g_hs2[(size_t)BSZ * TT * 2 * KH];

// ---------------- helpers -------------------------------------------------------
__device__ __forceinline__ float fsig(float x) {
    return __fdividef(1.0f, 1.0f + __expf(-x));
}
__device__ __forceinline__ float ftanh_(float x) {
    float e = __expf(2.0f * x);
    return 1.0f - __fdividef(2.0f, e + 1.0f);
}
__device__ __forceinline__ uint32_t smem_u32(const void* p) {
    uint32_t a;
    asm("{ .reg .u64 t; cvta.to.shared.u64 t, %1; cvt.u32.u64 %0, t; }" : "=r"(a) : "l"(p));
    return a;
}
__device__ __forceinline__ void mma16816(float* c, const uint32_t* a, const uint32_t* b) {
    asm volatile(
        "mma.sync.aligned.m16n8k16.row.col.f32.bf16.bf16.f32 "
        "{%0,%1,%2,%3}, {%4,%5,%6,%7}, {%8,%9}, {%0,%1,%2,%3};"
        : "+f"(c[0]), "+f"(c[1]), "+f"(c[2]), "+f"(c[3])
        : "r"(a[0]), "r"(a[1]), "r"(a[2]), "r"(a[3]), "r"(b[0]), "r"(b[1]));
}
#define LDSM4(r0, r1, r2, r3, addr)                                               \
    asm volatile("ldmatrix.sync.aligned.m8n8.x4.shared.b16 {%0,%1,%2,%3}, [%4];"  \
                 : "=r"(r0), "=r"(r1), "=r"(r2), "=r"(r3) : "r"(addr))
#define CPA16(dst, src)                                                           \
    asm volatile("cp.async.cg.shared.global [%0], [%1], 16;" :: "r"(dst), "l"(src))
#define CPA_COMMIT() asm volatile("cp.async.commit_group;")
#define CPA_WAIT1()  asm volatile("cp.async.wait_group 1;")
#define CPA_WAIT0()  asm volatile("cp.async.wait_group 0;")

// ---------------- prep kernels --------------------------------------------------
__global__ void prep_wsplit_kernel(const float* __restrict__ wih) {
    int idx = blockIdx.x * blockDim.x + threadIdx.x;
    if (idx >= MROWS * KDIM) return;
    int row = idx / KDIM, k = idx % KDIM;
    int d = row / NDR, r = row % NDR;
    int u = r >> 2, gate = r & 3;
    float v = 0.f;
    if (u < 300 && k < 300)
        v = wih[((size_t)d * 1200 + gate * 300 + u) * 300 + k];
    __nv_bfloat16 hi = __float2bfloat16(v);
    g_Wh[idx] = hi;
    g_Wl[idx] = __float2bfloat16(v - __bfloat162float(hi));
}

__global__ void prep_whhsplit_kernel(const float* __restrict__ whh) {
    int idx = blockIdx.x * blockDim.x + threadIdx.x;
    if (idx >= 2 * NDR * KH) return;
    int row = idx / KH, k = idx % KH;
    int d = row / NDR, r = row % NDR;
    int u = r >> 2, gate = r & 3;
    float v = 0.f;
    if (u < 300 && k < 300)
        v = whh[((size_t)d * 1200 + gate * 300 + u) * 300 + k];
    __nv_bfloat16 hi = __float2bfloat16(v);
    g_WHh[idx] = hi;
    g_WHl[idx] = __float2bfloat16(v - __bfloat162float(hi));
}

#define XS_BYTES (300 * 43 * 4)
__global__ void prep_xsplit_kernel(const float* __restrict__ x) {
    extern __shared__ float xs[];
    const int b = blockIdx.x;
    const int tid = threadIdx.x;
    for (int i = tid; i < 300 * TT; i += 256) xs[i] = x[(size_t)b * (300 * TT) + i];
    __syncthreads();
    for (int i = tid; i < TT * KDIM; i += 256) {
        int t = i / KDIM, k = i - t * KDIM;
        float v = (k < 300) ? xs[k * TT + t] : 0.f;
        __nv_bfloat16 hi = __float2bfloat16(v);
        size_t o = ((size_t)t * BSZ + b) * KDIM + k;
        g_Xh[o] = hi;
        g_Xl[o] = __float2bfloat16(v - __bfloat162float(hi));
    }
}

__global__ void prep_bias_kernel(const float* __restrict__ bih, const float* __restrict__ bhh) {
    int row = blockIdx.x * blockDim.x + threadIdx.x;
    if (row >= MROWS) return;
    int d = row / NDR, r = row % NDR;
    int u = r >> 2, gate = r & 3;
    float v = 0.f;
    if (u < 300)
        v = bih[(size_t)d * 1200 + gate * 300 + u] + bhh[(size_t)d * 1200 + gate * 300 + u];
    g_bias2560[row] = v;
}

__global__ void zero_state_kernel() {
    size_t i = (size_t)blockIdx.x * blockDim.x + threadIdx.x;
    size_t n = (size_t)2 * BSZ * KH;
    if (i >= n) return;
    g_cF[i] = 0.f;
    g_Hh[i] = __float2bfloat16(0.f);
    g_Hl[i] = __float2bfloat16(0.f);
}

// ---------------- staging + MMA core (shared between the two GEMM kernels) ------
#define STAGE_LOAD(ss, kc0, Asrc_h, Asrc_l, Bsrc_h, Bsrc_l, aRow0, bRow0, aStride, bStride) \
    {                                                                                       \
        uint32_t _sb = smb + (ss) * STAGEB;                                                 \
        _Pragma("unroll")                                                                   \
        for (int it = 0; it < 8; it++) {                                                    \
            int j = ((it & 1) << 8) + tid;                                                  \
            int r = j >> 2, c4 = j & 3;                                                     \
            uint32_t dst = _sb + (it >> 1) * TILEB + r * TRB + c4 * 16;                     \
            const __nv_bfloat16* src;                                                       \
            if ((it >> 1) == 0)      src = (Asrc_h) + (size_t)((aRow0) + r) * (aStride) + (kc0) + c4 * 8; \
            else if ((it >> 1) == 1) src = (Asrc_l) + (size_t)((aRow0) + r) * (aStride) + (kc0) + c4 * 8; \
            else if ((it >> 1) == 2) src = (Bsrc_h) + (size_t)((bRow0) + r) * (bStride) + (kc0) + c4 * 8; \
            else                     src = (Bsrc_l) + (size_t)((bRow0) + r) * (bStride) + (kc0) + c4 * 8; \
            CPA16(dst, src);                                                                \
        }                                                                                   \
        CPA_COMMIT();                                                                       \
    }

#define MMA_CHUNK(ss)                                                                       \
    {                                                                                       \
        uint32_t _sb = smb + (ss) * STAGEB;                                                 \
        uint32_t bAh = _sb, bAl = _sb + TILEB, bBh = _sb + 2 * TILEB, bBl = _sb + 3 * TILEB;\
        _Pragma("unroll")                                                                   \
        for (int ks = 0; ks < 2; ks++) {                                                    \
            const uint32_t kbb = ks * 32;                                                   \
            uint32_t aF[4][4], bHF[4][2], bLF[4][2];                                        \
            _Pragma("unroll")                                                               \
            for (int mt = 0; mt < 4; mt++)                                                  \
                LDSM4(aF[mt][0], aF[mt][1], aF[mt][2], aF[mt][3],                           \
                      bAh + aRowByte + mt * (16 * TRB) + kbb);                              \
            _Pragma("unroll")                                                               \
            for (int pp = 0; pp < 2; pp++)                                                  \
                LDSM4(bHF[2 * pp][0], bHF[2 * pp][1], bHF[2 * pp + 1][0], bHF[2 * pp + 1][1],\
                      bBh + bRowByte + pp * (16 * TRB) + kbb);                              \
            _Pragma("unroll")                                                               \
            for (int pp = 0; pp < 2; pp++)                                                  \
                LDSM4(bLF[2 * pp][0], bLF[2 * pp][1], bLF[2 * pp + 1][0], bLF[2 * pp + 1][1],\
                      bBl + bRowByte + pp * (16 * TRB) + kbb);                              \
            _Pragma("unroll")                                                               \
            for (int mt = 0; mt < 4; mt++)                                                  \
                _Pragma("unroll")                                                           \
                for (int nt = 0; nt < 4; nt++)                                              \
                    mma16816(acc[mt][nt], aF[mt], bHF[nt]);                                 \
            _Pragma("unroll")                                                               \
            for (int mt = 0; mt < 4; mt++)                                                  \
                _Pragma("unroll")                                                           \
                for (int nt = 0; nt < 4; nt++)                                              \
                    mma16816(acc[mt][nt], aF[mt], bLF[nt]);                                 \
            _Pragma("unroll")                                                               \
            for (int mt = 0; mt < 4; mt++)                                                  \
                LDSM4(aF[mt][0], aF[mt][1], aF[mt][2], aF[mt][3],                           \
                      bAl + aRowByte + mt * (16 * TRB) + kbb);                              \
            _Pragma("unroll")                                                               \
            for (int mt = 0; mt < 4; mt++)                                                  \
                _Pragma("unroll")                                                           \
                for (int nt = 0; nt < 4; nt++)                                              \
                    mma16816(acc[mt][nt], aF[mt], bHF[nt]);                                 \
        }                                                                                   \
    }

// ---------------- x-precompute GEMM, one timestep per launch --------------------
__global__ __launch_bounds__(256, 2)
void gemm_zx_kernel(int t) {
    extern __shared__ char sm[];
    const uint32_t smb = smem_u32(sm);
    const int tid  = threadIdx.x;
    const int lane = tid & 31;
    const int wid  = tid >> 5;
    const int wm   = wid & 1;
    const int wn   = wid >> 1;
    const int m0   = blockIdx.x * 128;
    const int btile = blockIdx.y;
    const int n0   = t * BSZ + btile * 128;   // column within g_X*

    const uint32_t aRowByte =
        (uint32_t)(wm * 64 + ((lane >> 3) & 1) * 8 + (lane & 7)) * TRB + (lane >> 4) * 16;
    const uint32_t bRowByte =
        (uint32_t)(wn * 32 + (lane >> 4) * 8 + (lane & 7)) * TRB + ((lane >> 3) & 1) * 16;

    float acc[4][4][4];
    #pragma unroll
    for (int mt = 0; mt < 4; mt++)
        #pragma unroll
        for (int nt = 0; nt < 4; nt++)
            #pragma unroll
            for (int i = 0; i < 4; i++) acc[mt][nt][i] = 0.f;

    STAGE_LOAD(0, 0, g_Wh, g_Wl, g_Xh, g_Xl, m0, n0, KDIM, KDIM);
    for (int chunk = 0; chunk < NCH; chunk++) {
        const int ss = chunk & 1;
        if (chunk + 1 < NCH) {
            STAGE_LOAD(ss ^ 1, (chunk + 1) * KC2, g_Wh, g_Wl, g_Xh, g_Xl, m0, n0, KDIM, KDIM);
            CPA_WAIT1();
        } else {
            CPA_WAIT0();
        }
        __syncthreads();
        MMA_CHUNK(ss);
        __syncthreads();
    }

    // fragment-order store (+bias)
    float4* zf = (float4*)(g_zxF + (((size_t)t * 20 + blockIdx.x) * 32 + btile) * 16384);
    const int rbase = m0 + wm * 64 + (lane >> 2);
    #pragma unroll
    for (int mt = 0; mt < 4; mt++) {
        int row = rbase + mt * 16;
        float br0 = g_bias2560[row];
        float br8 = g_bias2560[row + 8];
        #pragma unroll
        for (int nt = 0; nt < 4; nt++) {
            float4 v = make_float4(acc[mt][nt][0] + br0, acc[mt][nt][1] + br0,
                                   acc[mt][nt][2] + br8, acc[mt][nt][3] + br8);
            zf[(mt * 4 + nt) * 256 + tid] = v;
        }
    }
}

// ---------------- per-step recurrent GEMM (m=rows, n=batch) ---------------------
__global__ __launch_bounds__(256, 2)
void step_kernel(int t) {
    extern __shared__ char sm[];
    const uint32_t smb = smem_u32(sm);
    const int tid  = threadIdx.x;
    const int lane = tid & 31;
    const int wid  = tid >> 5;
    const int wm   = wid & 1;
    const int wn   = wid >> 1;
    const int mtl   = blockIdx.x;
    const int btile = blockIdx.y;
    const int d     = blockIdx.z;
    const int m0r   = mtl * 128;
    const int n0b   = btile * 128;
    const int p     = t & 1;
    const int q     = 1 - p;

    const __nv_bfloat16* WhB = g_WHh + (size_t)d * NDR * KH;
    const __nv_bfloat16* WlB = g_WHl + (size_t)d * NDR * KH;
    const __nv_bfloat16* HhB = g_Hh + (size_t)(p * 2 + d) * BSZ * KH;
    const __nv_bfloat16* HlB = g_Hl + (size_t)(p * 2 + d) * BSZ * KH;

    const uint32_t aRowByte =
        (uint32_t)(wm * 64 + ((lane >> 3) & 1) * 8 + (lane & 7)) * TRB + (lane >> 4) * 16;
    const uint32_t bRowByte =
        (uint32_t)(wn * 32 + (lane >> 4) * 8 + (lane & 7)) * TRB + ((lane >> 3) & 1) * 16;

    STAGE_LOAD(0, 0, WhB, WlB, HhB, HlB, m0r, n0b, KH, KH);

    float acc[4][4][4];
    {
        const float4* zf = (const float4*)(g_zxF +
            (((size_t)t * 20 + (d * 10 + mtl)) * 32 + btile) * 16384);
        #pragma unroll
        for (int mt = 0; mt < 4; mt++)
            #pragma unroll
            for (int nt = 0; nt < 4; nt++) {
                float4 v = zf[(mt * 4 + nt) * 256 + tid];
                acc[mt][nt][0] = v.x; acc[mt][nt][1] = v.y;
                acc[mt][nt][2] = v.z; acc[mt][nt][3] = v.w;
            }
    }

    for (int chunk = 0; chunk < NCH; chunk++) {
        const int ss = chunk & 1;
        if (chunk + 1 < NCH) {
            STAGE_LOAD(ss ^ 1, (chunk + 1) * KC2, WhB, WlB, HhB, HlB, m0r, n0b, KH, KH);
            CPA_WAIT1();
        } else {
            CPA_WAIT0();
        }
        __syncthreads();
        MMA_CHUNK(ss);
        __syncthreads();
    }
    __syncthreads();

    // ---- epilogue: 4-lane fragment transpose -> gates -> c update -> hT ----
    const int g = (lane >> 2) & 3;
    float* cS = g_cF + ((size_t)(d * 10 + mtl) * 32 + btile) * 4096;
    float* hT = (float*)sm;

    #pragma unroll
    for (int mt = 0; mt < 4; mt++) {
        #pragma unroll
        for (int nt = 0; nt < 4; nt++) {
            float v0 = acc[mt][nt][0], v1 = acc[mt][nt][1];
            float v2 = acc[mt][nt][2], v3 = acc[mt][nt][3];
            float a = (g & 2) ? v0 : v2;
            float b = (g & 2) ? v1 : v3;
            a = __shfl_xor_sync(0xffffffffu, a, 8);
            b = __shfl_xor_sync(0xffffffffu, b, 8);
            if (g & 2) { v0 = a; v1 = b; } else { v2 = a; v3 = b; }
            float c01 = (g & 1) ? v0 : v1;
            c01 = __shfl_xor_sync(0xffffffffu, c01, 4);
            if (g & 1) v0 = c01; else v1 = c01;
            float c23 = (g & 1) ? v2 : v3;
            c23 = __shfl_xor_sync(0xffffffffu, c23, 4);
            if (g & 1) v2 = c23; else v3 = c23;
            size_t ci = (size_t)(mt * 4 + nt) * 256 + tid;
            float co = cS[ci];
            float cn = fsig(v1) * co + fsig(v0) * ftanh_(v2);
            cS[ci] = cn;
            float h = fsig(v3) * ftanh_(cn);
            int U = wm * 16 + mt * 4 + ((lane >> 4) & 1) + 2 * (g >> 1);
            int N = wn * 32 + nt * 8 + (lane & 3) * 2 + (g & 1);
            hT[N * 33 + U] = h;
        }
    }
    __syncthreads();

    __nv_bfloat16* HhO = g_Hh + (size_t)(q * 2 + d) * BSZ * KH;
    __nv_bfloat16* HlO = g_Hl + (size_t)(q * 2 + d) * BSZ * KH;
    const int U0 = mtl * 32;
    for (int i = tid; i < 128 * 32; i += 256) {
        int bl = i >> 5, ul = i & 31;
        float h = hT[bl * 33 + ul];
        int b = n0b + bl;
        int u = U0 + ul;
        size_t hi = (size_t)b * KH + u;
        __nv_bfloat16 hh = __float2bfloat16(h);
        HhO[hi] = hh;
        HlO[hi] = __float2bfloat16(h - __bfloat162float(hh));
        g_hs2[((size_t)b * TT + t) * (2 * KH) + d * KH + u] = h;
    }
}

// ---------------- attention + FC epilogue ---------------------------------------
#define ATT_SMEM 119856

__global__ __launch_bounds__(256, 1)
void attn_kernel(const float* __restrict__ conv_w,
                 const float* __restrict__ fc_w,
                 const float* __restrict__ fc_b,
                 float* __restrict__ out) {
    extern __shared__ char smem[];
    float* fcT   = (float*)smem;
    float* hstar = (float*)(smem + 96000);
    float* cw    = (float*)(smem + 115200);
    float* e_sh  = cw + 300;
    float* l_sh  = e_sh + 704;
    float* p_sh  = l_sh + 80;

    const int tid = threadIdx.x;
    const int b0  = blockIdx.x * 16;

    for (int i = tid; i < 300; i += 256) cw[i] = conv_w[i];
    for (int i = tid; i < 300 * NCLS; i += 256) {
        int u = i / NCLS, cls = i - u * NCLS;
        fcT[i] = fc_w[(size_t)cls * 300 + u];
    }
    __syncthreads();

    {
        int wid = tid >> 5, lane = tid & 31;
        for (int task = wid; task < 16 * TT; task += 8) {
            int b = task / TT, t = task - b * TT;
            const float* hp = g_hs2 + ((size_t)(b0 + b) * TT + t) * (2 * KH);
            float s = 0.f;
            for (int u = lane; u < 300; u += 32)
                s += ftanh_(hp[u] + hp[KH + u]) * cw[u];
            #pragma unroll
            for (int o = 16; o > 0; o >>= 1) s += __shfl_xor_sync(0xffffffffu, s, o);
            if (lane == 0) e_sh[b * 44 + t] = s;
        }
    }
    __syncthreads();

    if (tid < 16) {
        float m = -1e30f;
        for (int t = 0; t < TT; t++) m = fmaxf(m, e_sh[tid * 44 + t]);
        float ss = 0.f;
        for (int t = 0; t < TT; t++) { float pz = __expf(e_sh[tid * 44 + t] - m); e_sh[tid * 44 + t] = pz; ss += pz; }
        float inv = 1.0f / ss;
        for (int t = 0; t < TT; t++) e_sh[tid * 44 + t] *= inv;
    }
    __syncthreads();

    for (int i = tid; i < 16 * 300; i += 256) {
        int b = i / 300, u = i - b * 300;
        const float* hp = g_hs2 + ((size_t)(b0 + b) * TT) * (2 * KH) + u;
        float acc = 0.f;
        for (int t = 0; t < TT; t++)
            acc += (hp[(size_t)t * (2 * KH)] + hp[(size_t)t * (2 * KH) + KH]) * e_sh[b * 44 + t];
        hstar[i] = ftanh_(acc);
    }
    __syncthreads();

    for (int b = 0; b < 16; b++) {
        if (tid < NCLS) {
            float acc = fc_b[tid];
            const float* hv = hstar + b * 300;
            for (int u = 0; u < 300; u++) acc += hv[u] * fcT[u * NCLS + tid];
            l_sh[tid] = acc;
        }
        __syncthreads();
        if (tid < NCLS) {
            float m = -1e30f;
            for (int j = 0; j < NCLS; j++) m = fmaxf(m, l_sh[j]);
            p_sh[tid] = __expf(l_sh[tid] - m);
        }
        __syncthreads();
        if (tid < NCLS) {
            float s = 0.f;
            for (int j = 0; j < NCLS; j++) s += p_sh[j];
            out[(size_t)(b0 + b) * NCLS + tid] = p_sh[tid] / s;
        }
        __syncthreads();
    }
}

// ---------------- launch ---------------------------------------------------------
extern "C" void kernel_launch(void* const* d_in, const int* in_sizes, int n_in,
                              void* d_out, int out_size) {
    const float* x      = (const float*)d_in[0];
    const float* w_ih   = (const float*)d_in[1];
    const float* w_hh   = (const float*)d_in[2];
    const float* b_ih   = (const float*)d_in[3];
    const float* b_hh   = (const float*)d_in[4];
    const float* conv_w = (const float*)d_in[5];
    const float* fc_w   = (const float*)d_in[6];
    const float* fc_b   = (const float*)d_in[7];
    float* out = (float*)d_out;

    cudaFuncSetAttribute(gemm_zx_kernel,     cudaFuncAttributeMaxDynamicSharedMemorySize, GS_BYTES);
    cudaFuncSetAttribute(step_kernel,        cudaFuncAttributeMaxDynamicSharedMemorySize, GS_BYTES);
    cudaFuncSetAttribute(attn_kernel,        cudaFuncAttributeMaxDynamicSharedMemorySize, ATT_SMEM);
    cudaFuncSetAttribute(prep_xsplit_kernel, cudaFuncAttributeMaxDynamicSharedMemorySize, XS_BYTES);

    // Fresh stream/events each call (host-side objects; host code runs once per
    // capture, so the cost is not in the timed replay). Intentionally not
    // destroyed: capture may still reference them when we return.
    cudaStream_t sB;
    cudaStreamCreateWithFlags(&sB, cudaStreamNonBlocking);
    cudaEvent_t evFork, evZx[TT];
    cudaEventCreateWithFlags(&evFork, cudaEventDisableTiming);
    for (int t = 0; t < TT; t++) cudaEventCreateWithFlags(&evZx[t], cudaEventDisableTiming);

    // zx-side preps on the main (captured origin) stream
    prep_wsplit_kernel<<<(MROWS * KDIM + 255) / 256, 256>>>(w_ih);
    prep_xsplit_kernel<<<BSZ, 256, XS_BYTES>>>(x);
    prep_bias_kernel<<<(MROWS + 255) / 256, 256>>>(b_ih, b_hh);

    // fork: zx per-t launches on sB
    cudaEventRecord(evFork, 0);
    cudaStreamWaitEvent(sB, evFork, 0);
    for (int t = 0; t < TT; t++) {
        gemm_zx_kernel<<<dim3(MTILES, 32), 256, GS_BYTES, sB>>>(t);
        cudaEventRecord(evZx[t], sB);
    }

    // step-side preps on the main stream (overlap with early zx work)
    prep_whhsplit_kernel<<<(2 * NDR * KH + 255) / 256, 256>>>(w_hh);
    zero_state_kernel<<<(int)(((size_t)2 * BSZ * KH + 255) / 256), 256>>>();

    // recurrence: step t gated on zx_t (waiting on evZx[TT-1] joins sB into capture)
    for (int t = 0; t < TT; t++) {
        cudaStreamWaitEvent(0, evZx[t], 0);
        step_kernel<<<dim3(10, 32, 2), 256, GS_BYTES>>>(t);
    }

    attn_kernel<<<BSZ / 16, 256, ATT_SMEM>>>(conv_w, fc_w, fc_b, out);
}

// round 11
// speedup vs baseline: 2.7496x; 1.1163x over previous
#include <cuda_runtime.h>
#include <cuda_bf16.h>
#include <math.h>
#include <stdint.h>

// Problem constants
#define BSZ   4096
#define HDIM  300
#define TT    43
#define NCLS  80

// GEMM shapes (x-precompute): m = 2560 weight rows, n = 4096 batch per t
#define MROWS 2560
#define KDIM  320
#define NCOLS 176128
#define MTILES 20
// recurrence
#define NDR   1280
#define KH    320

// pipeline staging: 3 stages, KC=32, unpadded 64B rows + SW64 swizzle
#define KC2    32
#define NCH    10          // 320/32
#define TILE64 8192        // 128 rows * 64 B
#define STG    32768       // 4 tiles
#define GS_BYTES (3 * STG) // 98304 -> 2 CTAs/SM

#define SW64(o) ((o) ^ (((o) >> 3) & 0x30))

// ---------------- device scratch ----------------------------------------------
__device__ __nv_bfloat16 g_Wh[(size_t)MROWS * KDIM];
__device__ __nv_bfloat16 g_Wl[(size_t)MROWS * KDIM];
__device__ __nv_bfloat16 g_Xh[(size_t)NCOLS * KDIM];
__device__ __nv_bfloat16 g_Xl[(size_t)NCOLS * KDIM];
__device__ float         g_zxF[(size_t)TT * 20 * 32 * 16384]; // fragment-order zx
__device__ float         g_bias2560[MROWS];
__device__ __nv_bfloat16 g_WHh[(size_t)2 * NDR * KH];
__device__ __nv_bfloat16 g_WHl[(size_t)2 * NDR * KH];
__device__ __nv_bfloat16 g_Hh[(size_t)2 * 2 * BSZ * KH];
__device__ __nv_bfloat16 g_Hl[(size_t)2 * 2 * BSZ * KH];
__device__ float         g_cF[(size_t)2 * 10 * 32 * 4096];
__device__ float         g_hs2[(size_t)BSZ * TT * 2 * KH];

// ---------------- helpers -------------------------------------------------------
__device__ __forceinline__ float fsig(float x) {
    return __fdividef(1.0f, 1.0f + __expf(-x));
}
__device__ __forceinline__ float ftanh_(float x) {
    float e = __expf(2.0f * x);
    return 1.0f - __fdividef(2.0f, e + 1.0f);
}
__device__ __forceinline__ uint32_t smem_u32(const void* p) {
    uint32_t a;
    asm("{ .reg .u64 t; cvta.to.shared.u64 t, %1; cvt.u32.u64 %0, t; }" : "=r"(a) : "l"(p));
    return a;
}
__device__ __forceinline__ void mma16816(float* c, const uint32_t* a, const uint32_t* b) {
    asm volatile(
        "mma.sync.aligned.m16n8k16.row.col.f32.bf16.bf16.f32 "
        "{%0,%1,%2,%3}, {%4,%5,%6,%7}, {%8,%9}, {%0,%1,%2,%3};"
        : "+f"(c[0]), "+f"(c[1]), "+f"(c[2]), "+f"(c[3])
        : "r"(a[0]), "r"(a[1]), "r"(a[2]), "r"(a[3]), "r"(b[0]), "r"(b[1]));
}
#define LDSM4(r0, r1, r2, r3, addr)                                               \
    asm volatile("ldmatrix.sync.aligned.m8n8.x4.shared.b16 {%0,%1,%2,%3}, [%4];"  \
                 : "=r"(r0), "=r"(r1), "=r"(r2), "=r"(r3) : "r"(addr))
#define CPA16(dst, src)                                                           \
    asm volatile("cp.async.cg.shared.global [%0], [%1], 16;" :: "r"(dst), "l"(src))
#define CPA_COMMIT() asm volatile("cp.async.commit_group;")
#define CPA_WAIT1()  asm volatile("cp.async.wait_group 1;")
#define CPA_WAIT0()  asm volatile("cp.async.wait_group 0;")

// ---------------- prep kernels --------------------------------------------------
__global__ void prep_wsplit_kernel(const float* __restrict__ wih) {
    int idx = blockIdx.x * blockDim.x + threadIdx.x;
    if (idx >= MROWS * KDIM) return;
    int row = idx / KDIM, k = idx % KDIM;
    int d = row / NDR, r = row % NDR;
    int u = r >> 2, gate = r & 3;
    float v = 0.f;
    if (u < 300 && k < 300)
        v = wih[((size_t)d * 1200 + gate * 300 + u) * 300 + k];
    __nv_bfloat16 hi = __float2bfloat16(v);
    g_Wh[idx] = hi;
    g_Wl[idx] = __float2bfloat16(v - __bfloat162float(hi));
}

__global__ void prep_whhsplit_kernel(const float* __restrict__ whh) {
    int idx = blockIdx.x * blockDim.x + threadIdx.x;
    if (idx >= 2 * NDR * KH) return;
    int row = idx / KH, k = idx % KH;
    int d = row / NDR, r = row % NDR;
    int u = r >> 2, gate = r & 3;
    float v = 0.f;
    if (u < 300 && k < 300)
        v = whh[((size_t)d * 1200 + gate * 300 + u) * 300 + k];
    __nv_bfloat16 hi = __float2bfloat16(v);
    g_WHh[idx] = hi;
    g_WHl[idx] = __float2bfloat16(v - __bfloat162float(hi));
}

#define XS_BYTES (300 * 43 * 4)
__global__ void prep_xsplit_kernel(const float* __restrict__ x) {
    extern __shared__ float xs[];
    const int b = blockIdx.x;
    const int tid = threadIdx.x;
    for (int i = tid; i < 300 * TT; i += 256) xs[i] = x[(size_t)b * (300 * TT) + i];
    __syncthreads();
    for (int i = tid; i < TT * KDIM; i += 256) {
        int t = i / KDIM, k = i - t * KDIM;
        float v = (k < 300) ? xs[k * TT + t] : 0.f;
        __nv_bfloat16 hi = __float2bfloat16(v);
        size_t o = ((size_t)t * BSZ + b) * KDIM + k;
        g_Xh[o] = hi;
        g_Xl[o] = __float2bfloat16(v - __bfloat162float(hi));
    }
}

__global__ void prep_bias_kernel(const float* __restrict__ bih, const float* __restrict__ bhh) {
    int row = blockIdx.x * blockDim.x + threadIdx.x;
    if (row >= MROWS) return;
    int d = row / NDR, r = row % NDR;
    int u = r >> 2, gate = r & 3;
    float v = 0.f;
    if (u < 300)
        v = bih[(size_t)d * 1200 + gate * 300 + u] + bhh[(size_t)d * 1200 + gate * 300 + u];
    g_bias2560[row] = v;
}

__global__ void zero_state_kernel() {
    size_t i = (size_t)blockIdx.x * blockDim.x + threadIdx.x;
    size_t n = (size_t)2 * BSZ * KH;
    if (i >= n) return;
    g_cF[i] = 0.f;
    g_Hh[i] = __float2bfloat16(0.f);
    g_Hl[i] = __float2bfloat16(0.f);
}

// ---------------- staging + MMA core ---------------------------------------------
// Stage: Ah @0, Al @TILE64, Bh @2*TILE64, Bl @3*TILE64; 64B rows, SW64 swizzle.
#define STAGE_LOAD(ss, kc0, Asrc_h, Asrc_l, Bsrc_h, Bsrc_l, aRow0, bRow0, aStride, bStride) \
    {                                                                                       \
        uint32_t _sb = smb + (uint32_t)(ss) * STG;                                          \
        _Pragma("unroll")                                                                   \
        for (int it = 0; it < 8; it++) {                                                    \
            int j = ((it & 1) << 8) + tid;                                                  \
            int r = j >> 2, c4 = j & 3;                                                     \
            uint32_t dst = _sb + (it >> 1) * TILE64 + SW64((uint32_t)(r * 64 + c4 * 16));   \
            const __nv_bfloat16* src;                                                       \
            if ((it >> 1) == 0)      src = (Asrc_h) + (size_t)((aRow0) + r) * (aStride) + (kc0) + c4 * 8; \
            else if ((it >> 1) == 1) src = (Asrc_l) + (size_t)((aRow0) + r) * (aStride) + (kc0) + c4 * 8; \
            else if ((it >> 1) == 2) src = (Bsrc_h) + (size_t)((bRow0) + r) * (bStride) + (kc0) + c4 * 8; \
            else                     src = (Bsrc_l) + (size_t)((bRow0) + r) * (bStride) + (kc0) + c4 * 8; \
            CPA16(dst, src);                                                                \
        }                                                                                   \
        CPA_COMMIT();                                                                       \
    }

// aOffS0/1, bOffS0/1 are per-lane pre-swizzled offsets (ks = 0, 1)
#define MMA_CHUNK(ss)                                                                       \
    {                                                                                       \
        uint32_t _sb = smb + (uint32_t)(ss) * STG;                                          \
        uint32_t bAh = _sb, bAl = _sb + TILE64, bBh = _sb + 2 * TILE64, bBl = _sb + 3 * TILE64; \
        _Pragma("unroll")                                                                   \
        for (int ks = 0; ks < 2; ks++) {                                                    \
            const uint32_t aOff = ks ? aOffS1 : aOffS0;                                     \
            const uint32_t bOff = ks ? bOffS1 : bOffS0;                                     \
            uint32_t aF[4][4], bHF[4][2], bLF[4][2];                                        \
            _Pragma("unroll")                                                               \
            for (int mt = 0; mt < 4; mt++)                                                  \
                LDSM4(aF[mt][0], aF[mt][1], aF[mt][2], aF[mt][3],                           \
                      bAh + aOff + mt * 1024);                                              \
            _Pragma("unroll")                                                               \
            for (int pp = 0; pp < 2; pp++)                                                  \
                LDSM4(bHF[2 * pp][0], bHF[2 * pp][1], bHF[2 * pp + 1][0], bHF[2 * pp + 1][1],\
                      bBh + bOff + pp * 1024);                                              \
            _Pragma("unroll")                                                               \
            for (int pp = 0; pp < 2; pp++)                                                  \
                LDSM4(bLF[2 * pp][0], bLF[2 * pp][1], bLF[2 * pp + 1][0], bLF[2 * pp + 1][1],\
                      bBl + bOff + pp * 1024);                                              \
            _Pragma("unroll")                                                               \
            for (int mt = 0; mt < 4; mt++)                                                  \
                _Pragma("unroll")                                                           \
                for (int nt = 0; nt < 4; nt++)                                              \
                    mma16816(acc[mt][nt], aF[mt], bHF[nt]);                                 \
            _Pragma("unroll")                                                               \
            for (int mt = 0; mt < 4; mt++)                                                  \
                _Pragma("unroll")                                                           \
                for (int nt = 0; nt < 4; nt++)                                              \
                    mma16816(acc[mt][nt], aF[mt], bLF[nt]);                                 \
            _Pragma("unroll")                                                               \
            for (int mt = 0; mt < 4; mt++)                                                  \
                LDSM4(aF[mt][0], aF[mt][1], aF[mt][2], aF[mt][3],                           \
                      bAl + aOff + mt * 1024);                                              \
            _Pragma("unroll")                                                               \
            for (int mt = 0; mt < 4; mt++)                                                  \
                _Pragma("unroll")                                                           \
                for (int nt = 0; nt < 4; nt++)                                              \
                    mma16816(acc[mt][nt], aF[mt], bHF[nt]);                                 \
        }                                                                                   \
    }

// per-lane linear offsets (swizzle applied with ks-offset included; additive
// terms mt*1024 / pp*1024 are above the XOR-affected bits, safe post-XOR)
#define LANE_OFFSETS()                                                                      \
    const uint32_t aLin = (uint32_t)(wm * 64 + ((lane >> 3) & 1) * 8 + (lane & 7)) * 64     \
                        + (lane >> 4) * 16;                                                 \
    const uint32_t bLin = (uint32_t)(wn * 32 + (lane >> 4) * 8 + (lane & 7)) * 64           \
                        + ((lane >> 3) & 1) * 16;                                           \
    const uint32_t aOffS0 = SW64(aLin), aOffS1 = SW64(aLin + 32);                           \
    const uint32_t bOffS0 = SW64(bLin), bOffS1 = SW64(bLin + 32);

// 3-stage mainloop: one barrier per chunk
#define PIPE_LOOP(Ah_, Al_, Bh_, Bl_, AR, BR, AS, BS)                                       \
    for (int chunk = 0; chunk < NCH; chunk++) {                                             \
        if (chunk < NCH - 1) { CPA_WAIT1(); } else { CPA_WAIT0(); }                         \
        __syncthreads();                                                                    \
        if (chunk + 2 < NCH)                                                                \
            STAGE_LOAD(sLoad, (chunk + 2) * KC2, Ah_, Al_, Bh_, Bl_, AR, BR, AS, BS);       \
        MMA_CHUNK(sComp);                                                                   \
        sComp = (sComp == 2) ? 0 : sComp + 1;                                               \
        sLoad = (sLoad == 2) ? 0 : sLoad + 1;                                               \
    }

// ---------------- x-precompute GEMM, one timestep per launch --------------------
__global__ __launch_bounds__(256, 2)
void gemm_zx_kernel(int t) {
    extern __shared__ char sm[];
    const uint32_t smb = smem_u32(sm);
    const int tid  = threadIdx.x;
    const int lane = tid & 31;
    const int wid  = tid >> 5;
    const int wm   = wid & 1;
    const int wn   = wid >> 1;
    const int m0   = blockIdx.x * 128;
    const int btile = blockIdx.y;
    const int n0   = t * BSZ + btile * 128;

    LANE_OFFSETS();

    float acc[4][4][4];
    #pragma unroll
    for (int mt = 0; mt < 4; mt++)
        #pragma unroll
        for (int nt = 0; nt < 4; nt++)
            #pragma unroll
            for (int i = 0; i < 4; i++) acc[mt][nt][i] = 0.f;

    STAGE_LOAD(0, 0,   g_Wh, g_Wl, g_Xh, g_Xl, m0, n0, KDIM, KDIM);
    STAGE_LOAD(1, KC2, g_Wh, g_Wl, g_Xh, g_Xl, m0, n0, KDIM, KDIM);
    int sComp = 0, sLoad = 2;
    PIPE_LOOP(g_Wh, g_Wl, g_Xh, g_Xl, m0, n0, KDIM, KDIM);

    // fragment-order store (+bias)
    float4* zf = (float4*)(g_zxF + (((size_t)t * 20 + blockIdx.x) * 32 + btile) * 16384);
    const int rbase = m0 + wm * 64 + (lane >> 2);
    #pragma unroll
    for (int mt = 0; mt < 4; mt++) {
        int row = rbase + mt * 16;
        float br0 = g_bias2560[row];
        float br8 = g_bias2560[row + 8];
        #pragma unroll
        for (int nt = 0; nt < 4; nt++) {
            float4 v = make_float4(acc[mt][nt][0] + br0, acc[mt][nt][1] + br0,
                                   acc[mt][nt][2] + br8, acc[mt][nt][3] + br8);
            zf[(mt * 4 + nt) * 256 + tid] = v;
        }
    }
}

// ---------------- per-step recurrent GEMM (m=rows, n=batch) ---------------------
__global__ __launch_bounds__(256, 2)
void step_kernel(int t) {
    extern __shared__ char sm[];
    const uint32_t smb = smem_u32(sm);
    const int tid  = threadIdx.x;
    const int lane = tid & 31;
    const int wid  = tid >> 5;
    const int wm   = wid & 1;
    const int wn   = wid >> 1;
    const int mtl   = blockIdx.x;
    const int btile = blockIdx.y;
    const int d     = blockIdx.z;
    const int m0r   = mtl * 128;
    const int n0b   = btile * 128;
    const int p     = t & 1;
    const int q     = 1 - p;

    const __nv_bfloat16* WhB = g_WHh + (size_t)d * NDR * KH;
    const __nv_bfloat16* WlB = g_WHl + (size_t)d * NDR * KH;
    const __nv_bfloat16* HhB = g_Hh + (size_t)(p * 2 + d) * BSZ * KH;
    const __nv_bfloat16* HlB = g_Hl + (size_t)(p * 2 + d) * BSZ * KH;

    LANE_OFFSETS();

    STAGE_LOAD(0, 0,   WhB, WlB, HhB, HlB, m0r, n0b, KH, KH);
    STAGE_LOAD(1, KC2, WhB, WlB, HhB, HlB, m0r, n0b, KH, KH);

    // init acc from fragment-order zx (overlaps with cp.async staging)
    float acc[4][4][4];
    {
        const float4* zf = (const float4*)(g_zxF +
            (((size_t)t * 20 + (d * 10 + mtl)) * 32 + btile) * 16384);
        #pragma unroll
        for (int mt = 0; mt < 4; mt++)
            #pragma unroll
            for (int nt = 0; nt < 4; nt++) {
                float4 v = zf[(mt * 4 + nt) * 256 + tid];
                acc[mt][nt][0] = v.x; acc[mt][nt][1] = v.y;
                acc[mt][nt][2] = v.z; acc[mt][nt][3] = v.w;
            }
    }

    int sComp = 0, sLoad = 2;
    PIPE_LOOP(WhB, WlB, HhB, HlB, m0r, n0b, KH, KH);
    __syncthreads();   // all ldmatrix of final chunk done before smem reuse

    // ---- epilogue: 4-lane fragment transpose -> gates -> c update -> hT ----
    const int g = (lane >> 2) & 3;
    float* cS = g_cF + ((size_t)(d * 10 + mtl) * 32 + btile) * 4096;
    float* hT = (float*)sm;   // [128 batch][33]

    #pragma unroll
    for (int mt = 0; mt < 4; mt++) {
        #pragma unroll
        for (int nt = 0; nt < 4; nt++) {
            float v0 = acc[mt][nt][0], v1 = acc[mt][nt][1];
            float v2 = acc[mt][nt][2], v3 = acc[mt][nt][3];
            float a = (g & 2) ? v0 : v2;
            float b = (g & 2) ? v1 : v3;
            a = __shfl_xor_sync(0xffffffffu, a, 8);
            b = __shfl_xor_sync(0xffffffffu, b, 8);
            if (g & 2) { v0 = a; v1 = b; } else { v2 = a; v3 = b; }
            float c01 = (g & 1) ? v0 : v1;
            c01 = __shfl_xor_sync(0xffffffffu, c01, 4);
            if (g & 1) v0 = c01; else v1 = c01;
            float c23 = (g & 1) ? v2 : v3;
            c23 = __shfl_xor_sync(0xffffffffu, c23, 4);
            if (g & 1) v2 = c23; else v3 = c23;
            size_t ci = (size_t)(mt * 4 + nt) * 256 + tid;
            float co = cS[ci];
            float cn = fsig(v1) * co + fsig(v0) * ftanh_(v2);
            cS[ci] = cn;
            float h = fsig(v3) * ftanh_(cn);
            int U = wm * 16 + mt * 4 + ((lane >> 4) & 1) + 2 * (g >> 1);
            int N = wn * 32 + nt * 8 + (lane & 3) * 2 + (g & 1);
            hT[N * 33 + U] = h;
        }
    }
    __syncthreads();

    __nv_bfloat16* HhO = g_Hh + (size_t)(q * 2 + d) * BSZ * KH;
    __nv_bfloat16* HlO = g_Hl + (size_t)(q * 2 + d) * BSZ * KH;
    const int U0 = mtl * 32;
    for (int i = tid; i < 128 * 32; i += 256) {
        int bl = i >> 5, ul = i & 31;
        float h = hT[bl * 33 + ul];
        int b = n0b + bl;
        int u = U0 + ul;
        size_t hi = (size_t)b * KH + u;
        __nv_bfloat16 hh = __float2bfloat16(h);
        HhO[hi] = hh;
        HlO[hi] = __float2bfloat16(h - __bfloat162float(hh));
        g_hs2[((size_t)b * TT + t) * (2 * KH) + d * KH + u] = h;
    }
}

// ---------------- attention + FC epilogue ---------------------------------------
#define ATT_SMEM 119856

__global__ __launch_bounds__(256, 1)
void attn_kernel(const float* __restrict__ conv_w,
                 const float* __restrict__ fc_w,
                 const float* __restrict__ fc_b,
                 float* __restrict__ out) {
    extern __shared__ char smem[];
    float* fcT   = (float*)smem;
    float* hstar = (float*)(smem + 96000);
    float* cw    = (float*)(smem + 115200);
    float* e_sh  = cw + 300;
    float* l_sh  = e_sh + 704;
    float* p_sh  = l_sh + 80;

    const int tid = threadIdx.x;
    const int b0  = blockIdx.x * 16;

    for (int i = tid; i < 300; i += 256) cw[i] = conv_w[i];
    for (int i = tid; i < 300 * NCLS; i += 256) {
        int u = i / NCLS, cls = i - u * NCLS;
        fcT[i] = fc_w[(size_t)cls * 300 + u];
    }
    __syncthreads();

    {
        int wid = tid >> 5, lane = tid & 31;
        for (int task = wid; task < 16 * TT; task += 8) {
            int b = task / TT, t = task - b * TT;
            const float* hp = g_hs2 + ((size_t)(b0 + b) * TT + t) * (2 * KH);
            float s = 0.f;
            for (int u = lane; u < 300; u += 32)
                s += ftanh_(hp[u] + hp[KH + u]) * cw[u];
            #pragma unroll
            for (int o = 16; o > 0; o >>= 1) s += __shfl_xor_sync(0xffffffffu, s, o);
            if (lane == 0) e_sh[b * 44 + t] = s;
        }
    }
    __syncthreads();

    if (tid < 16) {
        float m = -1e30f;
        for (int t = 0; t < TT; t++) m = fmaxf(m, e_sh[tid * 44 + t]);
        float ss = 0.f;
        for (int t = 0; t < TT; t++) { float pz = __expf(e_sh[tid * 44 + t] - m); e_sh[tid * 44 + t] = pz; ss += pz; }
        float inv = 1.0f / ss;
        for (int t = 0; t < TT; t++) e_sh[tid * 44 + t] *= inv;
    }
    __syncthreads();

    for (int i = tid; i < 16 * 300; i += 256) {
        int b = i / 300, u = i - b * 300;
        const float* hp = g_hs2 + ((size_t)(b0 + b) * TT) * (2 * KH) + u;
        float acc = 0.f;
        for (int t = 0; t < TT; t++)
            acc += (hp[(size_t)t * (2 * KH)] + hp[(size_t)t * (2 * KH) + KH]) * e_sh[b * 44 + t];
        hstar[i] = ftanh_(acc);
    }
    __syncthreads();

    for (int b = 0; b < 16; b++) {
        if (tid < NCLS) {
            float acc = fc_b[tid];
            const float* hv = hstar + b * 300;
            for (int u = 0; u < 300; u++) acc += hv[u] * fcT[u * NCLS + tid];
            l_sh[tid] = acc;
        }
        __syncthreads();
        if (tid < NCLS) {
            float m = -1e30f;
            for (int j = 0; j < NCLS; j++) m = fmaxf(m, l_sh[j]);
            p_sh[tid] = __expf(l_sh[tid] - m);
        }
        __syncthreads();
        if (tid < NCLS) {
            float s = 0.f;
            for (int j = 0; j < NCLS; j++) s += p_sh[j];
            out[(size_t)(b0 + b) * NCLS + tid] = p_sh[tid] / s;
        }
        __syncthreads();
    }
}

// ---------------- launch ---------------------------------------------------------
extern "C" void kernel_launch(void* const* d_in, const int* in_sizes, int n_in,
                              void* d_out, int out_size) {
    const float* x      = (const float*)d_in[0];
    const float* w_ih   = (const float*)d_in[1];
    const float* w_hh   = (const float*)d_in[2];
    const float* b_ih   = (const float*)d_in[3];
    const float* b_hh   = (const float*)d_in[4];
    const float* conv_w = (const float*)d_in[5];
    const float* fc_w   = (const float*)d_in[6];
    const float* fc_b   = (const float*)d_in[7];
    float* out = (float*)d_out;

    cudaFuncSetAttribute(gemm_zx_kernel,     cudaFuncAttributeMaxDynamicSharedMemorySize, GS_BYTES);
    cudaFuncSetAttribute(step_kernel,        cudaFuncAttributeMaxDynamicSharedMemorySize, GS_BYTES);
    cudaFuncSetAttribute(attn_kernel,        cudaFuncAttributeMaxDynamicSharedMemorySize, ATT_SMEM);
    cudaFuncSetAttribute(prep_xsplit_kernel, cudaFuncAttributeMaxDynamicSharedMemorySize, XS_BYTES);

    cudaStream_t sB;
    cudaStreamCreateWithFlags(&sB, cudaStreamNonBlocking);
    cudaEvent_t evFork, evZx[TT];
    cudaEventCreateWithFlags(&evFork, cudaEventDisableTiming);
    for (int t = 0; t < TT; t++) cudaEventCreateWithFlags(&evZx[t], cudaEventDisableTiming);

    // zx-side preps on the main (captured origin) stream
    prep_wsplit_kernel<<<(MROWS * KDIM + 255) / 256, 256>>>(w_ih);
    prep_xsplit_kernel<<<BSZ, 256, XS_BYTES>>>(x);
    prep_bias_kernel<<<(MROWS + 255) / 256, 256>>>(b_ih, b_hh);

    // fork: zx per-t launches on sB
    cudaEventRecord(evFork, 0);
    cudaStreamWaitEvent(sB, evFork, 0);
    for (int t = 0; t < TT; t++) {
        gemm_zx_kernel<<<dim3(MTILES, 32), 256, GS_BYTES, sB>>>(t);
        cudaEventRecord(evZx[t], sB);
    }

    // step-side preps on the main stream (overlap with early zx work)
    prep_whhsplit_kernel<<<(2 * NDR * KH + 255) / 256, 256>>>(w_hh);
    zero_state_kernel<<<(int)(((size_t)2 * BSZ * KH + 255) / 256), 256>>>();

    // recurrence: step t gated on zx_t
    for (int t = 0; t < TT; t++) {
        cudaStreamWaitEvent(0, evZx[t], 0);
        step_kernel<<<dim3(10, 32, 2), 256, GS_BYTES>>>(t);
    }

    attn_kernel<<<BSZ / 16, 256, ATT_SMEM>>>(conv_w, fc_w, fc_b, out);
}

// round 12
// speedup vs baseline: 6.0288x; 2.1926x over previous
#include <cuda_runtime.h>
#include <cuda_fp16.h>
#include <math.h>
#include <stdint.h>

// Problem constants
#define BSZ   4096
#define HDIM  300
#define TT    43
#define NCLS  80

// GEMM shapes (x-precompute): m = 2560 weight rows, n = 4096 batch per t
#define MROWS 2560
#define KDIM  320
#define NCOLS 176128
#define MTILES 20
// recurrence
#define NDR   1280
#define KH    320

// pipeline staging: 3 stages, KC=64, 128B rows, SW128 swizzle, fp16 single product
#define KC2    64
#define NCH    5           // 320/64
#define TILE16 16384       // 128 rows * 128 B
#define STG    32768       // A + B tiles
#define GS_BYTES (3 * STG) // 98304 -> 2 CTAs/SM

#define SW128(o) ((o) ^ (((o) >> 3) & 0x70))

// ---------------- device scratch ----------------------------------------------
__device__ __half g_Wh[(size_t)MROWS * KDIM];          // W_ih fp16 [row'][k]
__device__ __half g_Xh[(size_t)NCOLS * KDIM];          // X fp16 [col=(t*4096+b)][k]
__device__ float  g_zxF[(size_t)TT * 20 * 32 * 16384]; // fragment-order zx
__device__ float  g_bias2560[MROWS];
__device__ __half g_WHh[(size_t)2 * NDR * KH];         // W_hh fp16 [d][row'][k]
__device__ __half g_Hh[(size_t)2 * 2 * BSZ * KH];      // [buf][d][b][k]
__device__ float  g_cF[(size_t)2 * 10 * 32 * 4096];
__device__ float  g_hs2[(size_t)BSZ * TT * 2 * KH];

// ---------------- helpers -------------------------------------------------------
__device__ __forceinline__ float fsig(float x) {
    return __fdividef(1.0f, 1.0f + __expf(-x));
}
__device__ __forceinline__ float ftanh_(float x) {
    float e = __expf(2.0f * x);
    return 1.0f - __fdividef(2.0f, e + 1.0f);
}
__device__ __forceinline__ uint32_t smem_u32(const void* p) {
    uint32_t a;
    asm("{ .reg .u64 t; cvta.to.shared.u64 t, %1; cvt.u32.u64 %0, t; }" : "=r"(a) : "l"(p));
    return a;
}
__device__ __forceinline__ void mma16816(float* c, const uint32_t* a, const uint32_t* b) {
    asm volatile(
        "mma.sync.aligned.m16n8k16.row.col.f32.f16.f16.f32 "
        "{%0,%1,%2,%3}, {%4,%5,%6,%7}, {%8,%9}, {%0,%1,%2,%3};"
        : "+f"(c[0]), "+f"(c[1]), "+f"(c[2]), "+f"(c[3])
        : "r"(a[0]), "r"(a[1]), "r"(a[2]), "r"(a[3]), "r"(b[0]), "r"(b[1]));
}
#define LDSM4(r0, r1, r2, r3, addr)                                               \
    asm volatile("ldmatrix.sync.aligned.m8n8.x4.shared.b16 {%0,%1,%2,%3}, [%4];"  \
                 : "=r"(r0), "=r"(r1), "=r"(r2), "=r"(r3) : "r"(addr))
#define CPA16(dst, src)                                                           \
    asm volatile("cp.async.cg.shared.global [%0], [%1], 16;" :: "r"(dst), "l"(src))
#define CPA_COMMIT() asm volatile("cp.async.commit_group;")
#define CPA_WAIT1()  asm volatile("cp.async.wait_group 1;")
#define CPA_WAIT0()  asm volatile("cp.async.wait_group 0;")

// ---------------- prep kernels --------------------------------------------------
__global__ void prep_wsplit_kernel(const float* __restrict__ wih) {
    int idx = blockIdx.x * blockDim.x + threadIdx.x;
    if (idx >= MROWS * KDIM) return;
    int row = idx / KDIM, k = idx % KDIM;
    int d = row / NDR, r = row % NDR;
    int u = r >> 2, gate = r & 3;
    float v = 0.f;
    if (u < 300 && k < 300)
        v = wih[((size_t)d * 1200 + gate * 300 + u) * 300 + k];
    g_Wh[idx] = __float2half(v);
}

__global__ void prep_whhsplit_kernel(const float* __restrict__ whh) {
    int idx = blockIdx.x * blockDim.x + threadIdx.x;
    if (idx >= 2 * NDR * KH) return;
    int row = idx / KH, k = idx % KH;
    int d = row / NDR, r = row % NDR;
    int u = r >> 2, gate = r & 3;
    float v = 0.f;
    if (u < 300 && k < 300)
        v = whh[((size_t)d * 1200 + gate * 300 + u) * 300 + k];
    g_WHh[idx] = __float2half(v);
}

#define XS_BYTES (300 * 43 * 4)
__global__ void prep_xsplit_kernel(const float* __restrict__ x) {
    extern __shared__ float xs[];
    const int b = blockIdx.x;
    const int tid = threadIdx.x;
    for (int i = tid; i < 300 * TT; i += 256) xs[i] = x[(size_t)b * (300 * TT) + i];
    __syncthreads();
    for (int i = tid; i < TT * KDIM; i += 256) {
        int t = i / KDIM, k = i - t * KDIM;
        float v = (k < 300) ? xs[k * TT + t] : 0.f;
        g_Xh[((size_t)t * BSZ + b) * KDIM + k] = __float2half(v);
    }
}

__global__ void prep_bias_kernel(const float* __restrict__ bih, const float* __restrict__ bhh) {
    int row = blockIdx.x * blockDim.x + threadIdx.x;
    if (row >= MROWS) return;
    int d = row / NDR, r = row % NDR;
    int u = r >> 2, gate = r & 3;
    float v = 0.f;
    if (u < 300)
        v = bih[(size_t)d * 1200 + gate * 300 + u] + bhh[(size_t)d * 1200 + gate * 300 + u];
    g_bias2560[row] = v;
}

__global__ void zero_state_kernel() {
    size_t i = (size_t)blockIdx.x * blockDim.x + threadIdx.x;
    size_t n = (size_t)2 * BSZ * KH;
    if (i >= n) return;
    g_cF[i] = 0.f;
    g_Hh[i] = __float2half(0.f);
}

// ---------------- staging + MMA core ---------------------------------------------
// Stage: A @0, B @TILE16; 128B rows, SW128 swizzle.
#define STAGE_LOAD(ss, kc0, Asrc, Bsrc, aRow0, bRow0, aStride, bStride)                     \
    {                                                                                       \
        uint32_t _sb = smb + (uint32_t)(ss) * STG;                                          \
        _Pragma("unroll")                                                                   \
        for (int it = 0; it < 8; it++) {                                                    \
            int idx = ((it & 3) << 8) + tid;                                                \
            int r = idx >> 3, c8 = idx & 7;                                                 \
            uint32_t dst = _sb + (it >> 2) * TILE16 + SW128((uint32_t)(r * 128 + c8 * 16)); \
            const __half* src = ((it >> 2) == 0)                                            \
                ? (Asrc) + (size_t)((aRow0) + r) * (aStride) + (kc0) + c8 * 8               \
                : (Bsrc) + (size_t)((bRow0) + r) * (bStride) + (kc0) + c8 * 8;              \
            CPA16(dst, src);                                                                \
        }                                                                                   \
        CPA_COMMIT();                                                                       \
    }

// per-lane pre-swizzled ldmatrix offsets for the 4 k-slices of a KC=64 chunk
#define LANE_OFFSETS()                                                                      \
    const uint32_t aLin = (uint32_t)(wm * 64 + ((lane >> 3) & 1) * 8 + (lane & 7)) * 128    \
                        + (lane >> 4) * 16;                                                 \
    const uint32_t bLin = (uint32_t)(wn * 32 + (lane >> 4) * 8 + (lane & 7)) * 128          \
                        + ((lane >> 3) & 1) * 16;                                           \
    const uint32_t aOffK[4] = { SW128(aLin), SW128(aLin + 32), SW128(aLin + 64),            \
                                SW128(aLin + 96) };                                         \
    const uint32_t bOffK[4] = { SW128(bLin), SW128(bLin + 32), SW128(bLin + 64),            \
                                SW128(bLin + 96) };

#define MMA_CHUNK(ss)                                                                       \
    {                                                                                       \
        uint32_t _sb = smb + (uint32_t)(ss) * STG;                                          \
        uint32_t bA = _sb, bB = _sb + TILE16;                                               \
        _Pragma("unroll")                                                                   \
        for (int ks = 0; ks < 4; ks++) {                                                    \
            uint32_t aF[4][4], bF[4][2];                                                    \
            _Pragma("unroll")                                                               \
            for (int mt = 0; mt < 4; mt++)                                                  \
                LDSM4(aF[mt][0], aF[mt][1], aF[mt][2], aF[mt][3],                           \
                      bA + aOffK[ks] + mt * 2048);                                          \
            _Pragma("unroll")                                                               \
            for (int pp = 0; pp < 2; pp++)                                                  \
                LDSM4(bF[2 * pp][0], bF[2 * pp][1], bF[2 * pp + 1][0], bF[2 * pp + 1][1],   \
                      bB + bOffK[ks] + pp * 2048);                                          \
            _Pragma("unroll")                                                               \
            for (int mt = 0; mt < 4; mt++)                                                  \
                _Pragma("unroll")                                                           \
                for (int nt = 0; nt < 4; nt++)                                              \
                    mma16816(acc[mt][nt], aF[mt], bF[nt]);                                  \
        }                                                                                   \
    }

// 3-stage mainloop: one barrier per chunk
#define PIPE_LOOP(A_, B_, AR, BR, AS, BS)                                                   \
    for (int chunk = 0; chunk < NCH; chunk++) {                                             \
        if (chunk < NCH - 1) { CPA_WAIT1(); } else { CPA_WAIT0(); }                         \
        __syncthreads();                                                                    \
        if (chunk + 2 < NCH)                                                                \
            STAGE_LOAD(sLoad, (chunk + 2) * KC2, A_, B_, AR, BR, AS, BS);                   \
        MMA_CHUNK(sComp);                                                                   \
        sComp = (sComp == 2) ? 0 : sComp + 1;                                               \
        sLoad = (sLoad == 2) ? 0 : sLoad + 1;                                               \
    }

// ---------------- x-precompute GEMM, one timestep per launch --------------------
__global__ __launch_bounds__(256, 2)
void gemm_zx_kernel(int t) {
    extern __shared__ char sm[];
    const uint32_t smb = smem_u32(sm);
    const int tid  = threadIdx.x;
    const int lane = tid & 31;
    const int wid  = tid >> 5;
    const int wm   = wid & 1;
    const int wn   = wid >> 1;
    const int m0   = blockIdx.x * 128;
    const int btile = blockIdx.y;
    const int n0   = t * BSZ + btile * 128;

    LANE_OFFSETS();

    float acc[4][4][4];
    #pragma unroll
    for (int mt = 0; mt < 4; mt++)
        #pragma unroll
        for (int nt = 0; nt < 4; nt++)
            #pragma unroll
            for (int i = 0; i < 4; i++) acc[mt][nt][i] = 0.f;

    STAGE_LOAD(0, 0,   g_Wh, g_Xh, m0, n0, KDIM, KDIM);
    STAGE_LOAD(1, KC2, g_Wh, g_Xh, m0, n0, KDIM, KDIM);
    int sComp = 0, sLoad = 2;
    PIPE_LOOP(g_Wh, g_Xh, m0, n0, KDIM, KDIM);

    // fragment-order store (+bias)
    float4* zf = (float4*)(g_zxF + (((size_t)t * 20 + blockIdx.x) * 32 + btile) * 16384);
    const int rbase = m0 + wm * 64 + (lane >> 2);
    #pragma unroll
    for (int mt = 0; mt < 4; mt++) {
        int row = rbase + mt * 16;
        float br0 = g_bias2560[row];
        float br8 = g_bias2560[row + 8];
        #pragma unroll
        for (int nt = 0; nt < 4; nt++) {
            float4 v = make_float4(acc[mt][nt][0] + br0, acc[mt][nt][1] + br0,
                                   acc[mt][nt][2] + br8, acc[mt][nt][3] + br8);
            zf[(mt * 4 + nt) * 256 + tid] = v;
        }
    }
}

// ---------------- per-step recurrent GEMM (m=rows, n=batch) ---------------------
__global__ __launch_bounds__(256, 2)
void step_kernel(int t) {
    extern __shared__ char sm[];
    const uint32_t smb = smem_u32(sm);
    const int tid  = threadIdx.x;
    const int lane = tid & 31;
    const int wid  = tid >> 5;
    const int wm   = wid & 1;
    const int wn   = wid >> 1;
    const int mtl   = blockIdx.x;
    const int btile = blockIdx.y;
    const int d     = blockIdx.z;
    const int m0r   = mtl * 128;
    const int n0b   = btile * 128;
    const int p     = t & 1;
    const int q     = 1 - p;

    const __half* WhB = g_WHh + (size_t)d * NDR * KH;
    const __half* HhB = g_Hh + (size_t)(p * 2 + d) * BSZ * KH;

    LANE_OFFSETS();

    STAGE_LOAD(0, 0,   WhB, HhB, m0r, n0b, KH, KH);
    STAGE_LOAD(1, KC2, WhB, HhB, m0r, n0b, KH, KH);

    // init acc from fragment-order zx (overlaps with cp.async staging)
    float acc[4][4][4];
    {
        const float4* zf = (const float4*)(g_zxF +
            (((size_t)t * 20 + (d * 10 + mtl)) * 32 + btile) * 16384);
        #pragma unroll
        for (int mt = 0; mt < 4; mt++)
            #pragma unroll
            for (int nt = 0; nt < 4; nt++) {
                float4 v = zf[(mt * 4 + nt) * 256 + tid];
                acc[mt][nt][0] = v.x; acc[mt][nt][1] = v.y;
                acc[mt][nt][2] = v.z; acc[mt][nt][3] = v.w;
            }
    }

    int sComp = 0, sLoad = 2;
    PIPE_LOOP(WhB, HhB, m0r, n0b, KH, KH);
    __syncthreads();   // all ldmatrix of final chunk done before smem reuse

    // ---- epilogue: 4-lane fragment transpose -> gates -> c update -> hT ----
    const int g = (lane >> 2) & 3;
    float* cS = g_cF + ((size_t)(d * 10 + mtl) * 32 + btile) * 4096;
    float* hT = (float*)sm;   // [128 batch][33]

    #pragma unroll
    for (int mt = 0; mt < 4; mt++) {
        #pragma unroll
        for (int nt = 0; nt < 4; nt++) {
            float v0 = acc[mt][nt][0], v1 = acc[mt][nt][1];
            float v2 = acc[mt][nt][2], v3 = acc[mt][nt][3];
            float a = (g & 2) ? v0 : v2;
            float b = (g & 2) ? v1 : v3;
            a = __shfl_xor_sync(0xffffffffu, a, 8);
            b = __shfl_xor_sync(0xffffffffu, b, 8);
            if (g & 2) { v0 = a; v1 = b; } else { v2 = a; v3 = b; }
            float c01 = (g & 1) ? v0 : v1;
            c01 = __shfl_xor_sync(0xffffffffu, c01, 4);
            if (g & 1) v0 = c01; else v1 = c01;
            float c23 = (g & 1) ? v2 : v3;
            c23 = __shfl_xor_sync(0xffffffffu, c23, 4);
            if (g & 1) v2 = c23; else v3 = c23;
            size_t ci = (size_t)(mt * 4 + nt) * 256 + tid;
            float co = cS[ci];
            float cn = fsig(v1) * co + fsig(v0) * ftanh_(v2);
            cS[ci] = cn;
            float h = fsig(v3) * ftanh_(cn);
            int U = wm * 16 + mt * 4 + ((lane >> 4) & 1) + 2 * (g >> 1);
            int N = wn * 32 + nt * 8 + (lane & 3) * 2 + (g & 1);
            hT[N * 33 + U] = h;
        }
    }
    __syncthreads();

    __half* HhO = g_Hh + (size_t)(q * 2 + d) * BSZ * KH;
    const int U0 = mtl * 32;
    for (int i = tid; i < 128 * 32; i += 256) {
        int bl = i >> 5, ul = i & 31;
        float h = hT[bl * 33 + ul];
        int b = n0b + bl;
        int u = U0 + ul;
        HhO[(size_t)b * KH + u] = __float2half(h);
        g_hs2[((size_t)b * TT + t) * (2 * KH) + d * KH + u] = h;
    }
}

// ---------------- attention + FC epilogue ---------------------------------------
#define ATT_SMEM 119856

__global__ __launch_bounds__(256, 1)
void attn_kernel(const float* __restrict__ conv_w,
                 const float* __restrict__ fc_w,
                 const float* __restrict__ fc_b,
                 float* __restrict__ out) {
    extern __shared__ char smem[];
    float* fcT   = (float*)smem;
    float* hstar = (float*)(smem + 96000);
    float* cw    = (float*)(smem + 115200);
    float* e_sh  = cw + 300;
    float* l_sh  = e_sh + 704;
    float* p_sh  = l_sh + 80;

    const int tid = threadIdx.x;
    const int b0  = blockIdx.x * 16;

    for (int i = tid; i < 300; i += 256) cw[i] = conv_w[i];
    for (int i = tid; i < 300 * NCLS; i += 256) {
        int u = i / NCLS, cls = i - u * NCLS;
        fcT[i] = fc_w[(size_t)cls * 300 + u];
    }
    __syncthreads();

    {
        int wid = tid >> 5, lane = tid & 31;
        for (int task = wid; task < 16 * TT; task += 8) {
            int b = task / TT, t = task - b * TT;
            const float* hp = g_hs2 + ((size_t)(b0 + b) * TT + t) * (2 * KH);
            float s = 0.f;
            for (int u = lane; u < 300; u += 32)
                s += ftanh_(hp[u] + hp[KH + u]) * cw[u];
            #pragma unroll
            for (int o = 16; o > 0; o >>= 1) s += __shfl_xor_sync(0xffffffffu, s, o);
            if (lane == 0) e_sh[b * 44 + t] = s;
        }
    }
    __syncthreads();

    if (tid < 16) {
        float m = -1e30f;
        for (int t = 0; t < TT; t++) m = fmaxf(m, e_sh[tid * 44 + t]);
        float ss = 0.f;
        for (int t = 0; t < TT; t++) { float pz = __expf(e_sh[tid * 44 + t] - m); e_sh[tid * 44 + t] = pz; ss += pz; }
        float inv = 1.0f / ss;
        for (int t = 0; t < TT; t++) e_sh[tid * 44 + t] *= inv;
    }
    __syncthreads();

    for (int i = tid; i < 16 * 300; i += 256) {
        int b = i / 300, u = i - b * 300;
        const float* hp = g_hs2 + ((size_t)(b0 + b) * TT) * (2 * KH) + u;
        float acc = 0.f;
        for (int t = 0; t < TT; t++)
            acc += (hp[(size_t)t * (2 * KH)] + hp[(size_t)t * (2 * KH) + KH]) * e_sh[b * 44 + t];
        hstar[i] = ftanh_(acc);
    }
    __syncthreads();

    for (int b = 0; b < 16; b++) {
        if (tid < NCLS) {
            float acc = fc_b[tid];
            const float* hv = hstar + b * 300;
            for (int u = 0; u < 300; u++) acc += hv[u] * fcT[u * NCLS + tid];
            l_sh[tid] = acc;
        }
        __syncthreads();
        if (tid < NCLS) {
            float m = -1e30f;
            for (int j = 0; j < NCLS; j++) m = fmaxf(m, l_sh[j]);
            p_sh[tid] = __expf(l_sh[tid] - m);
        }
        __syncthreads();
        if (tid < NCLS) {
            float s = 0.f;
            for (int j = 0; j < NCLS; j++) s += p_sh[j];
            out[(size_t)(b0 + b) * NCLS + tid] = p_sh[tid] / s;
        }
        __syncthreads();
    }
}

// ---------------- launch ---------------------------------------------------------
extern "C" void kernel_launch(void* const* d_in, const int* in_sizes, int n_in,
                              void* d_out, int out_size) {
    const float* x      = (const float*)d_in[0];
    const float* w_ih   = (const float*)d_in[1];
    const float* w_hh   = (const float*)d_in[2];
    const float* b_ih   = (const float*)d_in[3];
    const float* b_hh   = (const float*)d_in[4];
    const float* conv_w = (const float*)d_in[5];
    const float* fc_w   = (const float*)d_in[6];
    const float* fc_b   = (const float*)d_in[7];
    float* out = (float*)d_out;

    cudaFuncSetAttribute(gemm_zx_kernel,     cudaFuncAttributeMaxDynamicSharedMemorySize, GS_BYTES);
    cudaFuncSetAttribute(step_kernel,        cudaFuncAttributeMaxDynamicSharedMemorySize, GS_BYTES);
    cudaFuncSetAttribute(attn_kernel,        cudaFuncAttributeMaxDynamicSharedMemorySize, ATT_SMEM);
    cudaFuncSetAttribute(prep_xsplit_kernel, cudaFuncAttributeMaxDynamicSharedMemorySize, XS_BYTES);

    cudaStream_t sB;
    cudaStreamCreateWithFlags(&sB, cudaStreamNonBlocking);
    cudaEvent_t evFork, evZx[TT];
    cudaEventCreateWithFlags(&evFork, cudaEventDisableTiming);
    for (int t = 0; t < TT; t++) cudaEventCreateWithFlags(&evZx[t], cudaEventDisableTiming);

    // zx-side preps on the main (captured origin) stream
    prep_wsplit_kernel<<<(MROWS * KDIM + 255) / 256, 256>>>(w_ih);
    prep_xsplit_kernel<<<BSZ, 256, XS_BYTES>>>(x);
    prep_bias_kernel<<<(MROWS + 255) / 256, 256>>>(b_ih, b_hh);

    // fork: zx per-t launches on sB
    cudaEventRecord(evFork, 0);
    cudaStreamWaitEvent(sB, evFork, 0);
    for (int t = 0; t < TT; t++) {
        gemm_zx_kernel<<<dim3(MTILES, 32), 256, GS_BYTES, sB>>>(t);
        cudaEventRecord(evZx[t], sB);
    }

    // step-side preps on the main stream (overlap with early zx work)
    prep_whhsplit_kernel<<<(2 * NDR * KH + 255) / 256, 256>>>(w_hh);
    zero_state_kernel<<<(int)(((size_t)2 * BSZ * KH + 255) / 256), 256>>>();

    // recurrence: step t gated on zx_t
    for (int t = 0; t < TT; t++) {
        cudaStreamWaitEvent(0, evZx[t], 0);
        step_kernel<<<dim3(10, 32, 2), 256, GS_BYTES>>>(t);
    }

    attn_kernel<<<BSZ / 16, 256, ATT_SMEM>>>(conv_w, fc_w, fc_b, out);
}